// round 3
// baseline (speedup 1.0000x reference)
#include <cuda_runtime.h>
#include <math.h>
#include <stdint.h>

#define NPTS 200000
#define TVSEG 1382400           // B*GZ2*GY2*GX2 = 2*16*180*240
#define NSEG_TOTAL 1634400      // 1382400 + 172800 + 57600 + 21600
#define NTILE 3125              // 200000 / 64

typedef unsigned long long u64;

// packed fp32x2 FMA (Blackwell sm_100+): d = a*b + d, two fp32 lanes
#define FFMA2(acc, a, b) \
    asm("fma.rn.f32x2 %0, %1, %2, %0;" : "+l"(acc) : "l"(a), "l"(b))
#define PACK2(d, f) \
    asm("mov.b64 %0, {%1, %1};" : "=l"(d) : "f"(f))
#define UNPK(lo, hi, u) \
    asm("mov.b64 {%0, %1}, %2;" : "=f"(lo), "=f"(hi) : "l"(u))

// ---------------- scratch (device globals; no allocation allowed) ----------
__device__ float g_reduced[NPTS * 64];                  // 51 MB
__device__ float g_segsum[(size_t)NSEG_TOTAL * 64];     // 418 MB (touched-only init)
__device__ float g_segcnt[NSEG_TOTAL];
__device__ int   g_lin[NPTS * 4];
__device__ float g_proj[NPTS * 64];
__device__ float g_tv[(size_t)TVSEG * 64];              // 354 MB (touched-only init)
__device__ int   g_lin2[NPTS];
__device__ unsigned char g_flag[TVSEG];

// ---------------- k0: zero touched segments + compute lin ------------------
__global__ void __launch_bounds__(256) k0_zero(const int* __restrict__ coords)
{
    int w = (blockIdx.x * 256 + threadIdx.x) >> 5;   // point
    int lane = threadIdx.x & 31;
    int j  = lane >> 3;          // scale 0..3
    int c8 = lane & 7;           // chunk 0..7

    int4 c = reinterpret_cast<const int4*>(coords)[w];
    int ps = (j == 0) ? 2 : (j == 1) ? 4 : (j == 2) ? 6 : 8;
    int dx = (j == 0) ? 240 : (j == 1) ? 120 : (j == 2) ? 80 : 60;
    int dy = (j == 0) ? 180 : (j == 1) ? 90 : (j == 2) ? 60 : 45;
    int dz = (j == 0) ? 16 : (j == 1) ? 8 : (j == 2) ? 6 : 4;
    int off = (j == 0) ? 0 : (j == 1) ? 1382400 : (j == 2) ? 1555200 : 1612800;

    int lin = ((c.x * dx + c.y / ps) * dy + c.z / ps) * dz + c.w / ps + off;
    if (c8 == 0) {
        g_lin[w * 4 + j] = lin;
        g_segcnt[lin] = 0.f;
    }
    float4 z4 = make_float4(0.f, 0.f, 0.f, 0.f);
    float4* dst = reinterpret_cast<float4*>(g_segsum + (size_t)lin * 64) + c8 * 2;
    dst[0] = z4;
    dst[1] = z4;
}

// ---------------- k1: reduced = relu(X@W_red + b) + atomic segment scatter -
__global__ void __launch_bounds__(256) k1_reduce(
    const float* __restrict__ input,
    const float* __restrict__ W_red, const float* __restrict__ b_red)
{
    __shared__ float sW[64 * 64];
    __shared__ float sb[64];
    for (int i = threadIdx.x; i < 64 * 64; i += 256) sW[i] = W_red[i];
    if (threadIdx.x < 64) sb[threadIdx.x] = b_red[threadIdx.x];
    __syncthreads();

    const int lane = threadIdx.x & 31;
    int w = (blockIdx.x * 256 + threadIdx.x) >> 5;

    float2 x2 = reinterpret_cast<const float2*>(input)[w * 32 + lane];
    float a0 = sb[2 * lane], a1 = sb[2 * lane + 1];
    #pragma unroll
    for (int k = 0; k < 64; ++k) {
        float xk = __shfl_sync(0xffffffffu, (k & 1) ? x2.y : x2.x, k >> 1);
        float2 w2 = reinterpret_cast<const float2*>(sW)[k * 32 + lane];
        a0 = fmaf(xk, w2.x, a0);
        a1 = fmaf(xk, w2.y, a1);
    }
    a0 = fmaxf(a0, 0.f); a1 = fmaxf(a1, 0.f);
    reinterpret_cast<float2*>(g_reduced)[w * 32 + lane] = make_float2(a0, a1);

    #pragma unroll
    for (int j = 0; j < 4; ++j) {
        int lin = g_lin[w * 4 + j];
        float* addr = g_segsum + (size_t)lin * 64 + 2 * lane;
        asm volatile("red.global.add.v2.f32 [%0], {%1, %2};"
                     :: "l"(addr), "f"(a0), "f"(a1) : "memory");
        if (lane == 0) atomicAdd(&g_segcnt[lin], 1.0f);
    }
}

// ---------------- k2: full per-point MLP chain, tiled GEMMs in SMEM --------
// tile = 64 points, 256 threads. f32x2 packed math (packing over point dim).
// SMEM float offsets:
#define OFF_FLW   0        // [4][64][32]  8192
#define OFF_FLB   8192     // 128
#define OFF_FCW   8320     // [32][32]     1024
#define OFF_FCSW  9344     // [4][32][32]  4096
#define OFF_FCSB  13440    // 128
#define OFF_OUTW  13568    // [32][64]     2048
#define OFF_LO1   15616    // [128][64]    8192
#define OFF_LO2   23808    // [64][64]     4096
#define OFF_LOB   27904    // 64
#define OFF_A     27968    // act buf [128][68] (k-major, pt contiguous) 8704
#define OFF_SF    36672    // sf [128][68] 8704
#define OFF_FS    45376    // [32][68] 2176
#define OFF_ZF    47552    // [32][68] 2176
#define OFF_H     49728    // [64][68] 4352
#define K2_SMEM_FLOATS 54080
#define K2_SMEM_BYTES (K2_SMEM_FLOATS * 4)
#define RL 68   // padded row length

__global__ void __launch_bounds__(256) k2_mlp(
    const float* __restrict__ flW, const float* __restrict__ flb,
    const float* __restrict__ fcW, const float* __restrict__ fcsW,
    const float* __restrict__ fcsb, const float* __restrict__ outW,
    const float* __restrict__ lo1, const float* __restrict__ lo2,
    const float* __restrict__ lob)
{
    extern __shared__ float sm[];
    const int tid = threadIdx.x;

    for (int i = tid; i < 8192; i += 256) sm[OFF_FLW + i]  = flW[i];
    for (int i = tid; i < 128;  i += 256) sm[OFF_FLB + i]  = flb[i];
    for (int i = tid; i < 1024; i += 256) sm[OFF_FCW + i]  = fcW[i];
    for (int i = tid; i < 4096; i += 256) sm[OFF_FCSW + i] = fcsW[i];
    for (int i = tid; i < 128;  i += 256) sm[OFF_FCSB + i] = fcsb[i];
    for (int i = tid; i < 2048; i += 256) sm[OFF_OUTW + i] = outW[i];
    for (int i = tid; i < 8192; i += 256) sm[OFF_LO1 + i]  = lo1[i];
    for (int i = tid; i < 4096; i += 256) sm[OFF_LO2 + i]  = lo2[i];
    if (tid < 64) sm[OFF_LOB + tid] = lob[tid];
    __syncthreads();

    for (int tile = blockIdx.x; tile < NTILE; tile += gridDim.x) {
        const int pbase = tile * 64;
        __syncthreads();

        // ===== Phase 1: two passes, 2 scales each: fkm gather + att GEMM ===
        #pragma unroll 1
        for (int pass = 0; pass < 2; ++pass) {
            const int j0 = pass * 2;
            // stage fkm_j into A[k][pt] (scale s at rows s*64..)
            {
                int pt = tid >> 2, q = tid & 3;
                #pragma unroll
                for (int s = 0; s < 2; ++s) {
                    int j = j0 + s;
                    int lin = g_lin[(pbase + pt) * 4 + j];
                    float inv = 1.f / fmaxf(g_segcnt[lin], 1.f);
                    const float4* src = reinterpret_cast<const float4*>(
                        g_segsum + (size_t)lin * 64 + q * 16);
                    float4 v0 = src[0], v1 = src[1], v2 = src[2], v3 = src[3];
                    float* dst = sm + OFF_A + (s * 64 + q * 16) * RL + pt;
                    dst[0*RL]=v0.x*inv; dst[1*RL]=v0.y*inv; dst[2*RL]=v0.z*inv; dst[3*RL]=v0.w*inv;
                    dst[4*RL]=v1.x*inv; dst[5*RL]=v1.y*inv; dst[6*RL]=v1.z*inv; dst[7*RL]=v1.w*inv;
                    dst[8*RL]=v2.x*inv; dst[9*RL]=v2.y*inv; dst[10*RL]=v2.z*inv; dst[11*RL]=v2.w*inv;
                    dst[12*RL]=v3.x*inv; dst[13*RL]=v3.y*inv; dst[14*RL]=v3.z*inv; dst[15*RL]=v3.w*inv;
                }
            }
            __syncthreads();
            // GEMM: 128 thr per scale, C[64pt][32c], micro 8pt x 2c, k=64
            {
                int s = tid >> 7, t2 = tid & 127;
                int c = (t2 >> 3) * 2, pt8 = (t2 & 7) * 8;
                int j = j0 + s;
                u64 acc[8];
                {
                    u64 pb0, pb1;
                    PACK2(pb0, sm[OFF_FLB + j * 32 + c]);
                    PACK2(pb1, sm[OFF_FLB + j * 32 + c + 1]);
                    acc[0]=pb0; acc[2]=pb0; acc[4]=pb0; acc[6]=pb0;
                    acc[1]=pb1; acc[3]=pb1; acc[5]=pb1; acc[7]=pb1;
                }
                const float* Ab = sm + OFF_A + s * 64 * RL + pt8;
                const float* Wb = sm + OFF_FLW + j * 64 * 32 + c;
                #pragma unroll 4
                for (int k = 0; k < 64; ++k) {
                    ulonglong2 a01 = *reinterpret_cast<const ulonglong2*>(Ab + k * RL);
                    ulonglong2 a23 = *reinterpret_cast<const ulonglong2*>(Ab + k * RL + 4);
                    float2 w = *reinterpret_cast<const float2*>(Wb + k * 32);
                    u64 w0, w1; PACK2(w0, w.x); PACK2(w1, w.y);
                    FFMA2(acc[0], a01.x, w0); FFMA2(acc[1], a01.x, w1);
                    FFMA2(acc[2], a01.y, w0); FFMA2(acc[3], a01.y, w1);
                    FFMA2(acc[4], a23.x, w0); FFMA2(acc[5], a23.x, w1);
                    FFMA2(acc[6], a23.y, w0); FFMA2(acc[7], a23.y, w1);
                }
                #pragma unroll
                for (int p = 0; p < 4; ++p)
                    #pragma unroll
                    for (int cc = 0; cc < 2; ++cc) {
                        float lo, hi; UNPK(lo, hi, acc[p * 2 + cc]);
                        *reinterpret_cast<float2*>(
                            sm + OFF_SF + (j * 32 + c + cc) * RL + pt8 + 2 * p)
                            = make_float2(fmaxf(lo, 0.f), fmaxf(hi, 0.f));
                    }
            }
            __syncthreads();
        }

        // ===== featS = sum_j sf_j  -> FS =================================
        for (int e = tid; e < 2048; e += 256) {
            int c = e >> 6, pt = e & 63;
            sm[OFF_FS + c * RL + pt] =
                  sm[OFF_SF + c * RL + pt]        + sm[OFF_SF + (32 + c) * RL + pt]
                + sm[OFF_SF + (64 + c) * RL + pt] + sm[OFF_SF + (96 + c) * RL + pt];
        }
        __syncthreads();

        // ===== z = relu(featS @ fcW) : C[64][32], micro 4pt x 2c ==========
        {
            int c = (tid >> 4) * 2, pt4 = (tid & 15) * 4;
            u64 acc[4] = {0ull, 0ull, 0ull, 0ull};
            #pragma unroll 4
            for (int k = 0; k < 32; ++k) {
                ulonglong2 a01 = *reinterpret_cast<const ulonglong2*>(
                    sm + OFF_FS + k * RL + pt4);
                float2 w = *reinterpret_cast<const float2*>(sm + OFF_FCW + k * 32 + c);
                u64 w0, w1; PACK2(w0, w.x); PACK2(w1, w.y);
                FFMA2(acc[0], a01.x, w0); FFMA2(acc[1], a01.x, w1);
                FFMA2(acc[2], a01.y, w0); FFMA2(acc[3], a01.y, w1);
            }
            #pragma unroll
            for (int p = 0; p < 2; ++p)
                #pragma unroll
                for (int cc = 0; cc < 2; ++cc) {
                    float lo, hi; UNPK(lo, hi, acc[p * 2 + cc]);
                    *reinterpret_cast<float2*>(
                        sm + OFF_ZF + (c + cc) * RL + pt4 + 2 * p)
                        = make_float2(fmaxf(lo, 0.f), fmaxf(hi, 0.f));
                }
        }
        __syncthreads();

        // ===== attention: att_j = sigmoid(z @ fcsW_j + b); sf_j *= att_j ===
        {
            int j = tid >> 6, t2 = tid & 63;
            int c = (t2 >> 3) * 4, pt8 = (t2 & 7) * 8;
            u64 acc[16];
            #pragma unroll
            for (int cc = 0; cc < 4; ++cc) {
                u64 pb; PACK2(pb, sm[OFF_FCSB + j * 32 + c + cc]);
                acc[0 * 4 + cc] = pb; acc[1 * 4 + cc] = pb;
                acc[2 * 4 + cc] = pb; acc[3 * 4 + cc] = pb;
            }
            #pragma unroll 4
            for (int k = 0; k < 32; ++k) {
                ulonglong2 a01 = *reinterpret_cast<const ulonglong2*>(
                    sm + OFF_ZF + k * RL + pt8);
                ulonglong2 a23 = *reinterpret_cast<const ulonglong2*>(
                    sm + OFF_ZF + k * RL + pt8 + 4);
                float4 w = *reinterpret_cast<const float4*>(
                    sm + OFF_FCSW + (j * 32 + k) * 32 + c);
                u64 w0, w1, w2, w3;
                PACK2(w0, w.x); PACK2(w1, w.y); PACK2(w2, w.z); PACK2(w3, w.w);
                FFMA2(acc[0],  a01.x, w0); FFMA2(acc[1],  a01.x, w1);
                FFMA2(acc[2],  a01.x, w2); FFMA2(acc[3],  a01.x, w3);
                FFMA2(acc[4],  a01.y, w0); FFMA2(acc[5],  a01.y, w1);
                FFMA2(acc[6],  a01.y, w2); FFMA2(acc[7],  a01.y, w3);
                FFMA2(acc[8],  a23.x, w0); FFMA2(acc[9],  a23.x, w1);
                FFMA2(acc[10], a23.x, w2); FFMA2(acc[11], a23.x, w3);
                FFMA2(acc[12], a23.y, w0); FFMA2(acc[13], a23.y, w1);
                FFMA2(acc[14], a23.y, w2); FFMA2(acc[15], a23.y, w3);
            }
            #pragma unroll
            for (int p = 0; p < 4; ++p)
                #pragma unroll
                for (int cc = 0; cc < 4; ++cc) {
                    float lo, hi; UNPK(lo, hi, acc[p * 4 + cc]);
                    float slo = __fdividef(1.f, 1.f + __expf(-lo));
                    float shi = __fdividef(1.f, 1.f + __expf(-hi));
                    float2* ptr = reinterpret_cast<float2*>(
                        sm + OFF_SF + (j * 32 + c + cc) * RL + pt8 + 2 * p);
                    float2 sv = *ptr;
                    *ptr = make_float2(sv.x * slo, sv.y * shi);
                }
        }
        __syncthreads();

        // ===== fp = sum_j sf_j*att_j -> FS ================================
        for (int e = tid; e < 2048; e += 256) {
            int c = e >> 6, pt = e & 63;
            sm[OFF_FS + c * RL + pt] =
                  sm[OFF_SF + c * RL + pt]        + sm[OFF_SF + (32 + c) * RL + pt]
                + sm[OFF_SF + (64 + c) * RL + pt] + sm[OFF_SF + (96 + c) * RL + pt];
        }
        __syncthreads();

        // ===== fused = fp @ outW -> A rows 64..127 (micro 8pt x 2c) =======
        {
            int c = (tid >> 3) * 2, pt8 = (tid & 7) * 8;
            u64 acc[8] = {0ull,0ull,0ull,0ull,0ull,0ull,0ull,0ull};
            #pragma unroll 4
            for (int k = 0; k < 32; ++k) {
                ulonglong2 a01 = *reinterpret_cast<const ulonglong2*>(
                    sm + OFF_FS + k * RL + pt8);
                ulonglong2 a23 = *reinterpret_cast<const ulonglong2*>(
                    sm + OFF_FS + k * RL + pt8 + 4);
                float2 w = *reinterpret_cast<const float2*>(sm + OFF_OUTW + k * 64 + c);
                u64 w0, w1; PACK2(w0, w.x); PACK2(w1, w.y);
                FFMA2(acc[0], a01.x, w0); FFMA2(acc[1], a01.x, w1);
                FFMA2(acc[2], a01.y, w0); FFMA2(acc[3], a01.y, w1);
                FFMA2(acc[4], a23.x, w0); FFMA2(acc[5], a23.x, w1);
                FFMA2(acc[6], a23.y, w0); FFMA2(acc[7], a23.y, w1);
            }
            #pragma unroll
            for (int p = 0; p < 4; ++p)
                #pragma unroll
                for (int cc = 0; cc < 2; ++cc) {
                    float lo, hi; UNPK(lo, hi, acc[p * 2 + cc]);
                    *reinterpret_cast<float2*>(
                        sm + OFF_A + (64 + c + cc) * RL + pt8 + 2 * p)
                        = make_float2(lo, hi);
                }
        }
        // stage reduced -> A rows 0..63 (independent of fused GEMM above)
        {
            int pt = tid >> 2, q = tid & 3;
            const float4* src = reinterpret_cast<const float4*>(
                g_reduced + (size_t)(pbase + pt) * 64 + q * 16);
            float4 v0 = src[0], v1 = src[1], v2 = src[2], v3 = src[3];
            float* dst = sm + OFF_A + (q * 16) * RL + pt;
            dst[0*RL]=v0.x; dst[1*RL]=v0.y; dst[2*RL]=v0.z; dst[3*RL]=v0.w;
            dst[4*RL]=v1.x; dst[5*RL]=v1.y; dst[6*RL]=v1.z; dst[7*RL]=v1.w;
            dst[8*RL]=v2.x; dst[9*RL]=v2.y; dst[10*RL]=v2.z; dst[11*RL]=v2.w;
            dst[12*RL]=v3.x; dst[13*RL]=v3.y; dst[14*RL]=v3.z; dst[15*RL]=v3.w;
        }
        __syncthreads();

        // ===== h = relu(A(128k) @ lo1) -> H ===============================
        {
            int c = (tid >> 3) * 2, pt8 = (tid & 7) * 8;
            u64 acc[8] = {0ull,0ull,0ull,0ull,0ull,0ull,0ull,0ull};
            #pragma unroll 4
            for (int k = 0; k < 128; ++k) {
                ulonglong2 a01 = *reinterpret_cast<const ulonglong2*>(
                    sm + OFF_A + k * RL + pt8);
                ulonglong2 a23 = *reinterpret_cast<const ulonglong2*>(
                    sm + OFF_A + k * RL + pt8 + 4);
                float2 w = *reinterpret_cast<const float2*>(sm + OFF_LO1 + k * 64 + c);
                u64 w0, w1; PACK2(w0, w.x); PACK2(w1, w.y);
                FFMA2(acc[0], a01.x, w0); FFMA2(acc[1], a01.x, w1);
                FFMA2(acc[2], a01.y, w0); FFMA2(acc[3], a01.y, w1);
                FFMA2(acc[4], a23.x, w0); FFMA2(acc[5], a23.x, w1);
                FFMA2(acc[6], a23.y, w0); FFMA2(acc[7], a23.y, w1);
            }
            #pragma unroll
            for (int p = 0; p < 4; ++p)
                #pragma unroll
                for (int cc = 0; cc < 2; ++cc) {
                    float lo, hi; UNPK(lo, hi, acc[p * 2 + cc]);
                    *reinterpret_cast<float2*>(
                        sm + OFF_H + (c + cc) * RL + pt8 + 2 * p)
                        = make_float2(fmaxf(lo, 0.f), fmaxf(hi, 0.f));
                }
        }
        __syncthreads();

        // ===== proj = h @ lo2 + lob -> gmem ===============================
        {
            int c = (tid >> 3) * 2, pt8 = (tid & 7) * 8;
            u64 acc[8];
            {
                u64 pb0, pb1;
                PACK2(pb0, sm[OFF_LOB + c]);
                PACK2(pb1, sm[OFF_LOB + c + 1]);
                acc[0]=pb0; acc[2]=pb0; acc[4]=pb0; acc[6]=pb0;
                acc[1]=pb1; acc[3]=pb1; acc[5]=pb1; acc[7]=pb1;
            }
            #pragma unroll 4
            for (int k = 0; k < 64; ++k) {
                ulonglong2 a01 = *reinterpret_cast<const ulonglong2*>(
                    sm + OFF_H + k * RL + pt8);
                ulonglong2 a23 = *reinterpret_cast<const ulonglong2*>(
                    sm + OFF_H + k * RL + pt8 + 4);
                float2 w = *reinterpret_cast<const float2*>(sm + OFF_LO2 + k * 64 + c);
                u64 w0, w1; PACK2(w0, w.x); PACK2(w1, w.y);
                FFMA2(acc[0], a01.x, w0); FFMA2(acc[1], a01.x, w1);
                FFMA2(acc[2], a01.y, w0); FFMA2(acc[3], a01.y, w1);
                FFMA2(acc[4], a23.x, w0); FFMA2(acc[5], a23.x, w1);
                FFMA2(acc[6], a23.y, w0); FFMA2(acc[7], a23.y, w1);
            }
            #pragma unroll
            for (int p = 0; p < 4; ++p) {
                float l0, h0, l1, h1;
                UNPK(l0, h0, acc[p * 2 + 0]);
                UNPK(l1, h1, acc[p * 2 + 1]);
                int pt = pbase + pt8 + 2 * p;
                *reinterpret_cast<float2*>(g_proj + (size_t)pt * 64 + c)
                    = make_float2(l0, l1);
                *reinterpret_cast<float2*>(g_proj + (size_t)(pt + 1) * 64 + c)
                    = make_float2(h0, h1);
            }
        }
    }
}

// ---------------- k3pre: sentinel-init touched tv segments + flags + lin2 --
__global__ void __launch_bounds__(256) k3pre(const int* __restrict__ bxyz,
                                             float* __restrict__ out)
{
    int w = (blockIdx.x * 256 + threadIdx.x) >> 5;
    int lane = threadIdx.x & 31;
    int4 b = reinterpret_cast<const int4*>(bxyz)[w];
    int lin2 = ((b.x * 16 + b.w) * 180 + b.z) * 240 + b.y;
    if (lane == 0) {
        g_flag[lin2] = 1;
        g_lin2[w] = lin2;
        out[(size_t)NPTS * 64 + (size_t)TVSEG * 64 + w] = (float)lin2;
    }
    if (lane < 16) {
        uint4 s = make_uint4(0xFFFFFFFFu, 0xFFFFFFFFu, 0xFFFFFFFFu, 0xFFFFFFFFu);
        reinterpret_cast<uint4*>(g_tv + (size_t)lin2 * 64)[lane] = s;
    }
}

// ---------------- k3: gather by inv + atomic segment-max -------------------
__device__ __forceinline__ void atomicMaxFloat(float* addr, float v)
{
    if (v >= 0.f) atomicMax((int*)addr, __float_as_int(v));
    else          atomicMin((unsigned int*)addr, __float_as_uint(v));
}

__global__ void __launch_bounds__(256) k3_scatter(const int* __restrict__ inv,
                                                  float* __restrict__ out)
{
    int idx = blockIdx.x * 256 + threadIdx.x;
    int n = idx >> 6, c = idx & 63;
    int src = inv[n];
    float v = g_proj[src * 64 + c];
    out[idx] = v;
    int lin2 = g_lin2[n];
    atomicMaxFloat(&g_tv[(size_t)lin2 * 64 + c], v);
}

// ---------------- k4: finalize tv -> out (flag-gated) ----------------------
__global__ void __launch_bounds__(256) k4_final(float* __restrict__ out)
{
    size_t idx = (size_t)blockIdx.x * 256 + threadIdx.x;   // float4 units
    size_t seg = idx >> 4;
    float4 v = make_float4(0.f, 0.f, 0.f, 0.f);
    if (g_flag[seg])
        v = reinterpret_cast<const float4*>(g_tv)[idx];
    reinterpret_cast<float4*>(out + (size_t)NPTS * 64)[idx] = v;
}

// ---------------- launch ---------------------------------------------------
extern "C" void kernel_launch(void* const* d_in, const int* in_sizes, int n_in,
                              void* d_out, int out_size)
{
    const float* input     = (const float*)d_in[0];
    const int*   coords    = (const int*)  d_in[1];
    const int*   inv       = (const int*)  d_in[2];
    const int*   bxyz      = (const int*)  d_in[3];
    const float* W_red     = (const float*)d_in[4];
    const float* b_red     = (const float*)d_in[5];
    const float* fc_list_W = (const float*)d_in[6];
    const float* fc_list_b = (const float*)d_in[7];
    const float* fcs_W     = (const float*)d_in[8];
    const float* fcs_b     = (const float*)d_in[9];
    const float* fc_W      = (const float*)d_in[10];
    const float* out_fc_W  = (const float*)d_in[11];
    const float* lo_W1     = (const float*)d_in[12];
    const float* lo_W2     = (const float*)d_in[13];
    const float* lo_b2     = (const float*)d_in[14];
    float* out = (float*)d_out;

    void* p;
    cudaGetSymbolAddress(&p, g_flag);
    cudaMemsetAsync(p, 0, TVSEG);

    cudaFuncSetAttribute(k2_mlp, cudaFuncAttributeMaxDynamicSharedMemorySize,
                         K2_SMEM_BYTES);

    k0_zero<<<25000, 256>>>(coords);
    k1_reduce<<<25000, 256>>>(input, W_red, b_red);
    k2_mlp<<<592, 256, K2_SMEM_BYTES>>>(fc_list_W, fc_list_b, fc_W, fcs_W,
                                        fcs_b, out_fc_W, lo_W1, lo_W2, lo_b2);
    k3pre<<<25000, 256>>>(bxyz, out);
    k3_scatter<<<50000, 256>>>(inv, out);
    k4_final<<<86400, 256>>>(out);
}

// round 5
// speedup vs baseline: 1.0650x; 1.0650x over previous
#include <cuda_runtime.h>
#include <math.h>
#include <stdint.h>

#define NPTS 200000
#define TVSEG 1382400           // B*GZ2*GY2*GX2 = 2*16*180*240
#define NSEG_TOTAL 1634400      // 1382400 + 172800 + 57600 + 21600

typedef unsigned long long u64;

// packed fp32x2 FMA (Blackwell sm_100+): d = a*b + d, two fp32 lanes
#define FFMA2(acc, a, b) \
    asm("fma.rn.f32x2 %0, %1, %2, %0;" : "+l"(acc) : "l"(a), "l"(b))
#define PACK2(d, f) \
    asm("mov.b64 %0, {%1, %1};" : "=l"(d) : "f"(f))
#define UNPK(lo, hi, u) \
    asm("mov.b64 {%0, %1}, %2;" : "=f"(lo), "=f"(hi) : "l"(u))

// ---------------- scratch (device globals; no allocation allowed) ----------
__device__ float g_reduced[NPTS * 64];                  // 51 MB
__device__ float g_segsum[(size_t)NSEG_TOTAL * 64];     // 418 MB (touched-only init)
__device__ float g_segcnt[NSEG_TOTAL];
__device__ int   g_lin[NPTS * 4];
__device__ float g_sf[(size_t)NPTS * 128];              // 102 MB spill
__device__ float g_proj[NPTS * 64];
__device__ float g_tv[(size_t)TVSEG * 64];              // 354 MB (touched-only init)
__device__ int   g_lin2[NPTS];
__device__ unsigned char g_flag[TVSEG];

// ---------------- k0: zero touched segments + compute lin ------------------
__global__ void __launch_bounds__(256) k0_zero(const int* __restrict__ coords)
{
    int w = (blockIdx.x * 256 + threadIdx.x) >> 5;   // point
    int lane = threadIdx.x & 31;
    int j  = lane >> 3;          // scale 0..3
    int c8 = lane & 7;           // chunk 0..7

    int4 c = reinterpret_cast<const int4*>(coords)[w];
    int ps = (j == 0) ? 2 : (j == 1) ? 4 : (j == 2) ? 6 : 8;
    int dx = (j == 0) ? 240 : (j == 1) ? 120 : (j == 2) ? 80 : 60;
    int dy = (j == 0) ? 180 : (j == 1) ? 90 : (j == 2) ? 60 : 45;
    int dz = (j == 0) ? 16 : (j == 1) ? 8 : (j == 2) ? 6 : 4;
    int off = (j == 0) ? 0 : (j == 1) ? 1382400 : (j == 2) ? 1555200 : 1612800;

    int lin = ((c.x * dx + c.y / ps) * dy + c.z / ps) * dz + c.w / ps + off;
    if (c8 == 0) {
        g_lin[w * 4 + j] = lin;
        g_segcnt[lin] = 0.f;
    }
    float4 z4 = make_float4(0.f, 0.f, 0.f, 0.f);
    float4* dst = reinterpret_cast<float4*>(g_segsum + (size_t)lin * 64) + c8 * 2;
    dst[0] = z4;
    dst[1] = z4;
}

// ---------------- k1: reduced = relu(X@W_red + b) + atomic segment scatter -
__global__ void __launch_bounds__(256) k1_reduce(
    const float* __restrict__ input,
    const float* __restrict__ W_red, const float* __restrict__ b_red)
{
    __shared__ float sW[64 * 64];
    __shared__ float sb[64];
    for (int i = threadIdx.x; i < 64 * 64; i += 256) sW[i] = W_red[i];
    if (threadIdx.x < 64) sb[threadIdx.x] = b_red[threadIdx.x];
    __syncthreads();

    const int lane = threadIdx.x & 31;
    int w = (blockIdx.x * 256 + threadIdx.x) >> 5;

    float2 x2 = reinterpret_cast<const float2*>(input)[w * 32 + lane];
    float a0 = sb[2 * lane], a1 = sb[2 * lane + 1];
    #pragma unroll
    for (int k = 0; k < 64; ++k) {
        float xk = __shfl_sync(0xffffffffu, (k & 1) ? x2.y : x2.x, k >> 1);
        float2 w2 = reinterpret_cast<const float2*>(sW)[k * 32 + lane];
        a0 = fmaf(xk, w2.x, a0);
        a1 = fmaf(xk, w2.y, a1);
    }
    a0 = fmaxf(a0, 0.f); a1 = fmaxf(a1, 0.f);
    reinterpret_cast<float2*>(g_reduced)[w * 32 + lane] = make_float2(a0, a1);

    #pragma unroll
    for (int j = 0; j < 4; ++j) {
        int lin = g_lin[w * 4 + j];
        float* addr = g_segsum + (size_t)lin * 64 + 2 * lane;
        asm volatile("red.global.add.v2.f32 [%0], {%1, %2};"
                     :: "l"(addr), "f"(a0), "f"(a1) : "memory");
        if (lane == 0) atomicAdd(&g_segcnt[lin], 1.0f);
    }
}

// ---------------- k2: merged per-point MLP chain (thread-per-point) --------
// f32x2 packed over CHANNEL dim: weight pairs come pre-packed from SMEM.
// One ulonglong2 = 4 floats = 2 f32x2 pairs; a row of C channels = C/4
// ulonglong2. acc[i] holds channels (2i, 2i+1).
// SMEM float offsets (weights only, 27968 floats = 112 KB -> 2 CTA/SM):
#define OFF_FLW   0        // [4][64][32]  8192
#define OFF_FLB   8192     // 128
#define OFF_FCW   8320     // [32][32]     1024
#define OFF_FCSW  9344     // [4][32][32]  4096
#define OFF_FCSB  13440    // 128
#define OFF_OUTW  13568    // [32][64]     2048
#define OFF_LO1   15616    // [128][64]    8192
#define OFF_LO2   23808    // [64][64]     4096
#define OFF_LOB   27904    // 64
#define K2_SMEM_BYTES (27968 * 4)

__global__ void __launch_bounds__(256) k2_mlp(
    const float* __restrict__ flW, const float* __restrict__ flb,
    const float* __restrict__ fcW, const float* __restrict__ fcsW,
    const float* __restrict__ fcsb, const float* __restrict__ outW,
    const float* __restrict__ lo1, const float* __restrict__ lo2,
    const float* __restrict__ lob)
{
    extern __shared__ float sm[];
    const int tid = threadIdx.x;

    for (int i = tid; i < 8192; i += 256) sm[OFF_FLW + i]  = flW[i];
    for (int i = tid; i < 128;  i += 256) sm[OFF_FLB + i]  = flb[i];
    for (int i = tid; i < 1024; i += 256) sm[OFF_FCW + i]  = fcW[i];
    for (int i = tid; i < 4096; i += 256) sm[OFF_FCSW + i] = fcsW[i];
    for (int i = tid; i < 128;  i += 256) sm[OFF_FCSB + i] = fcsb[i];
    for (int i = tid; i < 2048; i += 256) sm[OFF_OUTW + i] = outW[i];
    for (int i = tid; i < 8192; i += 256) sm[OFF_LO1 + i]  = lo1[i];
    for (int i = tid; i < 4096; i += 256) sm[OFF_LO2 + i]  = lo2[i];
    if (tid < 64) sm[OFF_LOB + tid] = lob[tid];
    __syncthreads();

    const int n = blockIdx.x * 256 + tid;
    if (n >= NPTS) return;

    // ===== Phase A: per scale, att_j = relu(fkm_j @ flW_j + flb_j) =========
    float featS[32];
    #pragma unroll
    for (int c = 0; c < 32; ++c) featS[c] = 0.f;

    #pragma unroll 1
    for (int j = 0; j < 4; ++j) {
        int lin = g_lin[n * 4 + j];
        float inv = 1.f / fmaxf(g_segcnt[lin], 1.f);
        float4 fk[16];
        {
            const float4* src = reinterpret_cast<const float4*>(
                g_segsum + (size_t)lin * 64);
            #pragma unroll
            for (int i = 0; i < 16; ++i) fk[i] = src[i];
        }
        u64 acc[16];
        {
            const u64* bp = reinterpret_cast<const u64*>(sm + OFF_FLB + j * 32);
            #pragma unroll
            for (int i = 0; i < 16; ++i) acc[i] = bp[i];
        }
        // row of 32 ch = 8 ulonglong2
        const ulonglong2* Wj = reinterpret_cast<const ulonglong2*>(sm + OFF_FLW)
                               + (size_t)j * 64 * 8;
        #pragma unroll
        for (int k = 0; k < 64; ++k) {
            float4 v = fk[k >> 2];
            float xs = ((k & 3) == 0) ? v.x : ((k & 3) == 1) ? v.y
                       : ((k & 3) == 2) ? v.z : v.w;
            xs *= inv;
            u64 xp; PACK2(xp, xs);
            const ulonglong2* W = Wj + k * 8;
            #pragma unroll
            for (int i = 0; i < 8; ++i) {
                ulonglong2 wv = W[i];
                FFMA2(acc[2 * i],     xp, wv.x);
                FFMA2(acc[2 * i + 1], xp, wv.y);
            }
        }
        float4* sfdst = reinterpret_cast<float4*>(g_sf + (size_t)n * 128 + j * 32);
        #pragma unroll
        for (int i = 0; i < 8; ++i) {
            float l0, h0, l1, h1;
            UNPK(l0, h0, acc[2 * i]);
            UNPK(l1, h1, acc[2 * i + 1]);
            l0 = fmaxf(l0, 0.f); h0 = fmaxf(h0, 0.f);
            l1 = fmaxf(l1, 0.f); h1 = fmaxf(h1, 0.f);
            sfdst[i] = make_float4(l0, h0, l1, h1);
            featS[4 * i + 0] += l0; featS[4 * i + 1] += h0;
            featS[4 * i + 2] += l1; featS[4 * i + 3] += h1;
        }
    }

    // ===== z = relu(featS @ fcW) ==========================================
    float z[32];
    {
        u64 acc[16];
        #pragma unroll
        for (int i = 0; i < 16; ++i) acc[i] = 0ull;
        const ulonglong2* Wb = reinterpret_cast<const ulonglong2*>(sm + OFF_FCW);
        #pragma unroll
        for (int k = 0; k < 32; ++k) {
            u64 xp; PACK2(xp, featS[k]);
            const ulonglong2* W = Wb + k * 8;
            #pragma unroll
            for (int i = 0; i < 8; ++i) {
                ulonglong2 wv = W[i];
                FFMA2(acc[2 * i],     xp, wv.x);
                FFMA2(acc[2 * i + 1], xp, wv.y);
            }
        }
        #pragma unroll
        for (int i = 0; i < 16; ++i) {
            float lo, hi; UNPK(lo, hi, acc[i]);
            z[2 * i] = fmaxf(lo, 0.f); z[2 * i + 1] = fmaxf(hi, 0.f);
        }
    }

    // ===== attention: fp = sum_j sf_j * sigmoid(z @ fcsW_j + fcsb_j) ======
    float fp[32];
    #pragma unroll
    for (int c = 0; c < 32; ++c) fp[c] = 0.f;

    #pragma unroll 1
    for (int j = 0; j < 4; ++j) {
        u64 acc[16];
        {
            const u64* bp = reinterpret_cast<const u64*>(sm + OFF_FCSB + j * 32);
            #pragma unroll
            for (int i = 0; i < 16; ++i) acc[i] = bp[i];
        }
        const ulonglong2* Wj = reinterpret_cast<const ulonglong2*>(sm + OFF_FCSW)
                               + (size_t)j * 32 * 8;
        #pragma unroll
        for (int k = 0; k < 32; ++k) {
            u64 xp; PACK2(xp, z[k]);
            const ulonglong2* W = Wj + k * 8;
            #pragma unroll
            for (int i = 0; i < 8; ++i) {
                ulonglong2 wv = W[i];
                FFMA2(acc[2 * i],     xp, wv.x);
                FFMA2(acc[2 * i + 1], xp, wv.y);
            }
        }
        const float4* sfsrc = reinterpret_cast<const float4*>(
            g_sf + (size_t)n * 128 + j * 32);
        #pragma unroll
        for (int i = 0; i < 8; ++i) {
            float4 sv = sfsrc[i];
            float l0, h0, l1, h1;
            UNPK(l0, h0, acc[2 * i]);
            UNPK(l1, h1, acc[2 * i + 1]);
            float a0 = __fdividef(1.f, 1.f + __expf(-l0));
            float a1 = __fdividef(1.f, 1.f + __expf(-h0));
            float a2 = __fdividef(1.f, 1.f + __expf(-l1));
            float a3 = __fdividef(1.f, 1.f + __expf(-h1));
            fp[4 * i + 0] = fmaf(sv.x, a0, fp[4 * i + 0]);
            fp[4 * i + 1] = fmaf(sv.y, a1, fp[4 * i + 1]);
            fp[4 * i + 2] = fmaf(sv.z, a2, fp[4 * i + 2]);
            fp[4 * i + 3] = fmaf(sv.w, a3, fp[4 * i + 3]);
        }
    }

    // ===== fused = fp @ outW  (64 ch; row = 16 ulonglong2) ================
    float fused[64];
    {
        u64 acc[32];
        #pragma unroll
        for (int i = 0; i < 32; ++i) acc[i] = 0ull;
        const ulonglong2* Wb = reinterpret_cast<const ulonglong2*>(sm + OFF_OUTW);
        #pragma unroll
        for (int k = 0; k < 32; ++k) {
            u64 xp; PACK2(xp, fp[k]);
            const ulonglong2* W = Wb + k * 16;
            #pragma unroll
            for (int i = 0; i < 16; ++i) {
                ulonglong2 wv = W[i];
                FFMA2(acc[2 * i],     xp, wv.x);
                FFMA2(acc[2 * i + 1], xp, wv.y);
            }
        }
        #pragma unroll
        for (int i = 0; i < 32; ++i) {
            float lo, hi; UNPK(lo, hi, acc[i]);
            fused[2 * i] = lo; fused[2 * i + 1] = hi;
        }
    }

    // ===== h = relu([reduced, fused] @ lo1) ===============================
    float h[64];
    {
        u64 acc[32];
        #pragma unroll
        for (int i = 0; i < 32; ++i) acc[i] = 0ull;
        const ulonglong2* Wb = reinterpret_cast<const ulonglong2*>(sm + OFF_LO1);
        const float4* rsrc = reinterpret_cast<const float4*>(
            g_reduced + (size_t)n * 64);
        #pragma unroll
        for (int k = 0; k < 64; ++k) {
            float4 r = rsrc[k >> 2];
            float xs = ((k & 3) == 0) ? r.x : ((k & 3) == 1) ? r.y
                       : ((k & 3) == 2) ? r.z : r.w;
            u64 xp; PACK2(xp, xs);
            const ulonglong2* W = Wb + k * 16;
            #pragma unroll
            for (int i = 0; i < 16; ++i) {
                ulonglong2 wv = W[i];
                FFMA2(acc[2 * i],     xp, wv.x);
                FFMA2(acc[2 * i + 1], xp, wv.y);
            }
        }
        #pragma unroll
        for (int k = 0; k < 64; ++k) {
            u64 xp; PACK2(xp, fused[k]);
            const ulonglong2* W = Wb + (64 + k) * 16;
            #pragma unroll
            for (int i = 0; i < 16; ++i) {
                ulonglong2 wv = W[i];
                FFMA2(acc[2 * i],     xp, wv.x);
                FFMA2(acc[2 * i + 1], xp, wv.y);
            }
        }
        #pragma unroll
        for (int i = 0; i < 32; ++i) {
            float lo, hi; UNPK(lo, hi, acc[i]);
            h[2 * i] = fmaxf(lo, 0.f); h[2 * i + 1] = fmaxf(hi, 0.f);
        }
    }

    // ===== proj = h @ lo2 + lob ===========================================
    {
        u64 acc[32];
        {
            const u64* bp = reinterpret_cast<const u64*>(sm + OFF_LOB);
            #pragma unroll
            for (int i = 0; i < 32; ++i) acc[i] = bp[i];
        }
        const ulonglong2* Wb = reinterpret_cast<const ulonglong2*>(sm + OFF_LO2);
        #pragma unroll
        for (int k = 0; k < 64; ++k) {
            u64 xp; PACK2(xp, h[k]);
            const ulonglong2* W = Wb + k * 16;
            #pragma unroll
            for (int i = 0; i < 16; ++i) {
                ulonglong2 wv = W[i];
                FFMA2(acc[2 * i],     xp, wv.x);
                FFMA2(acc[2 * i + 1], xp, wv.y);
            }
        }
        float4* pdst = reinterpret_cast<float4*>(g_proj + (size_t)n * 64);
        #pragma unroll
        for (int i = 0; i < 16; ++i) {
            float l0, h0, l1, h1;
            UNPK(l0, h0, acc[2 * i]);
            UNPK(l1, h1, acc[2 * i + 1]);
            pdst[i] = make_float4(l0, h0, l1, h1);
        }
    }
}

// ---------------- k3pre: sentinel-init touched tv segments + flags + lin2 --
__global__ void __launch_bounds__(256) k3pre(const int* __restrict__ bxyz,
                                             float* __restrict__ out)
{
    int w = (blockIdx.x * 256 + threadIdx.x) >> 5;
    int lane = threadIdx.x & 31;
    int4 b = reinterpret_cast<const int4*>(bxyz)[w];
    int lin2 = ((b.x * 16 + b.w) * 180 + b.z) * 240 + b.y;
    if (lane == 0) {
        g_flag[lin2] = 1;
        g_lin2[w] = lin2;
        out[(size_t)NPTS * 64 + (size_t)TVSEG * 64 + w] = (float)lin2;
    }
    if (lane < 16) {
        uint4 s = make_uint4(0xFFFFFFFFu, 0xFFFFFFFFu, 0xFFFFFFFFu, 0xFFFFFFFFu);
        reinterpret_cast<uint4*>(g_tv + (size_t)lin2 * 64)[lane] = s;
    }
}

// ---------------- k3: gather by inv + atomic segment-max -------------------
__device__ __forceinline__ void atomicMaxFloat(float* addr, float v)
{
    if (v >= 0.f) atomicMax((int*)addr, __float_as_int(v));
    else          atomicMin((unsigned int*)addr, __float_as_uint(v));
}

__global__ void __launch_bounds__(256) k3_scatter(const int* __restrict__ inv,
                                                  float* __restrict__ out)
{
    int idx = blockIdx.x * 256 + threadIdx.x;
    int n = idx >> 6, c = idx & 63;
    int src = inv[n];
    float v = g_proj[src * 64 + c];
    out[idx] = v;
    int lin2 = g_lin2[n];
    atomicMaxFloat(&g_tv[(size_t)lin2 * 64 + c], v);
}

// ---------------- k4: finalize tv -> out (flag-gated) ----------------------
__global__ void __launch_bounds__(256) k4_final(float* __restrict__ out)
{
    size_t idx = (size_t)blockIdx.x * 256 + threadIdx.x;   // float4 units
    size_t seg = idx >> 4;
    float4 v = make_float4(0.f, 0.f, 0.f, 0.f);
    if (g_flag[seg])
        v = reinterpret_cast<const float4*>(g_tv)[idx];
    reinterpret_cast<float4*>(out + (size_t)NPTS * 64)[idx] = v;
}

// ---------------- launch ---------------------------------------------------
extern "C" void kernel_launch(void* const* d_in, const int* in_sizes, int n_in,
                              void* d_out, int out_size)
{
    const float* input     = (const float*)d_in[0];
    const int*   coords    = (const int*)  d_in[1];
    const int*   inv       = (const int*)  d_in[2];
    const int*   bxyz      = (const int*)  d_in[3];
    const float* W_red     = (const float*)d_in[4];
    const float* b_red     = (const float*)d_in[5];
    const float* fc_list_W = (const float*)d_in[6];
    const float* fc_list_b = (const float*)d_in[7];
    const float* fcs_W     = (const float*)d_in[8];
    const float* fcs_b     = (const float*)d_in[9];
    const float* fc_W      = (const float*)d_in[10];
    const float* out_fc_W  = (const float*)d_in[11];
    const float* lo_W1     = (const float*)d_in[12];
    const float* lo_W2     = (const float*)d_in[13];
    const float* lo_b2     = (const float*)d_in[14];
    float* out = (float*)d_out;

    void* p;
    cudaGetSymbolAddress(&p, g_flag);
    cudaMemsetAsync(p, 0, TVSEG);

    cudaFuncSetAttribute(k2_mlp, cudaFuncAttributeMaxDynamicSharedMemorySize,
                         K2_SMEM_BYTES);

    k0_zero<<<25000, 256>>>(coords);
    k1_reduce<<<25000, 256>>>(input, W_red, b_red);
    k2_mlp<<<782, 256, K2_SMEM_BYTES>>>(fc_list_W, fc_list_b, fc_W, fcs_W,
                                        fcs_b, out_fc_W, lo_W1, lo_W2, lo_b2);
    k3pre<<<25000, 256>>>(bxyz, out);
    k3_scatter<<<50000, 256>>>(inv, out);
    k4_final<<<86400, 256>>>(out);
}

// round 6
// speedup vs baseline: 1.1419x; 1.0721x over previous
#include <cuda_runtime.h>
#include <math.h>
#include <stdint.h>

#define NPTS 200000
#define TVSEG 1382400           // B*GZ2*GY2*GX2 = 2*16*180*240
#define NSEG_TOTAL 1634400      // 1382400 + 172800 + 57600 + 21600
#define SEGCAP 200704           // 784*256, >= max touched segs per scale

// ---------------- scratch (device globals; no allocation allowed) ----------
__device__ float g_reduced[NPTS * 64];                  // 51 MB
__device__ float g_segsum[(size_t)NSEG_TOTAL * 64];     // 418 MB (touched-only init)
__device__ float g_segcnt[NSEG_TOTAL];
__device__ int   g_lin[NPTS * 4];
__device__ int   g_segidx[NSEG_TOTAL];                  // lin -> att slot (init -1)
__device__ int   g_seglist[4 * SEGCAP];                 // compact touched lists
__device__ int   g_cnt4[4];
__device__ float g_att[(size_t)4 * SEGCAP * 32];        // 103 MB, fits L2
__device__ float g_proj[NPTS * 64];
__device__ float g_tv[(size_t)TVSEG * 64];              // 354 MB (touched-only init)
__device__ int   g_lin2[NPTS];
__device__ unsigned char g_flag[TVSEG];

// ---------------- k0: zero touched segs + claim tickets + compute lin ------
__global__ void __launch_bounds__(256) k0_zero(const int* __restrict__ coords)
{
    int w = (blockIdx.x * 256 + threadIdx.x) >> 5;   // point
    int lane = threadIdx.x & 31;
    int j  = lane >> 3;          // scale 0..3
    int c8 = lane & 7;           // chunk 0..7

    int4 c = reinterpret_cast<const int4*>(coords)[w];
    int ps = (j == 0) ? 2 : (j == 1) ? 4 : (j == 2) ? 6 : 8;
    int dx = (j == 0) ? 240 : (j == 1) ? 120 : (j == 2) ? 80 : 60;
    int dy = (j == 0) ? 180 : (j == 1) ? 90 : (j == 2) ? 60 : 45;
    int dz = (j == 0) ? 16 : (j == 1) ? 8 : (j == 2) ? 6 : 4;
    int off = (j == 0) ? 0 : (j == 1) ? 1382400 : (j == 2) ? 1555200 : 1612800;

    int lin = ((c.x * dx + c.y / ps) * dy + c.z / ps) * dz + c.w / ps + off;
    if (c8 == 0) {
        g_lin[w * 4 + j] = lin;
        g_segcnt[lin] = 0.f;
        int old = atomicCAS(&g_segidx[lin], -1, 0x40000000);
        if (old == -1) {
            int t = atomicAdd(&g_cnt4[j], 1);
            g_seglist[j * SEGCAP + t] = lin;
            g_segidx[lin] = j * SEGCAP + t;
        }
    }
    float4 z4 = make_float4(0.f, 0.f, 0.f, 0.f);
    float4* dst = reinterpret_cast<float4*>(g_segsum + (size_t)lin * 64) + c8 * 2;
    dst[0] = z4;
    dst[1] = z4;
}

// ---------------- k1: reduced = relu(X@W_red + b) + atomic segment scatter -
__global__ void __launch_bounds__(256) k1_reduce(
    const float* __restrict__ input,
    const float* __restrict__ W_red, const float* __restrict__ b_red)
{
    __shared__ float sW[64 * 64];
    __shared__ float sb[64];
    for (int i = threadIdx.x; i < 64 * 64; i += 256) sW[i] = W_red[i];
    if (threadIdx.x < 64) sb[threadIdx.x] = b_red[threadIdx.x];
    __syncthreads();

    const int lane = threadIdx.x & 31;
    int w = (blockIdx.x * 256 + threadIdx.x) >> 5;

    float2 x2 = reinterpret_cast<const float2*>(input)[w * 32 + lane];
    float a0 = sb[2 * lane], a1 = sb[2 * lane + 1];
    #pragma unroll
    for (int k = 0; k < 64; ++k) {
        float xk = __shfl_sync(0xffffffffu, (k & 1) ? x2.y : x2.x, k >> 1);
        float2 w2 = reinterpret_cast<const float2*>(sW)[k * 32 + lane];
        a0 = fmaf(xk, w2.x, a0);
        a1 = fmaf(xk, w2.y, a1);
    }
    a0 = fmaxf(a0, 0.f); a1 = fmaxf(a1, 0.f);
    reinterpret_cast<float2*>(g_reduced)[w * 32 + lane] = make_float2(a0, a1);

    #pragma unroll
    for (int j = 0; j < 4; ++j) {
        int lin = g_lin[w * 4 + j];
        float* addr = g_segsum + (size_t)lin * 64 + 2 * lane;
        asm volatile("red.global.add.v2.f32 [%0], {%1, %2};"
                     :: "l"(addr), "f"(a0), "f"(a1) : "memory");
        if (lane == 0) atomicAdd(&g_segcnt[lin], 1.0f);
    }
}

// ---------------- k2_seg: per touched segment, att = relu(mean @ flW + b) --
__global__ void __launch_bounds__(256) k2_seg(
    const float* __restrict__ flW, const float* __restrict__ flb)
{
    __shared__ float sW[8192];
    __shared__ float sb[128];
    for (int i = threadIdx.x; i < 8192; i += 256) sW[i] = flW[i];
    if (threadIdx.x < 128) sb[threadIdx.x] = flb[threadIdx.x];
    __syncthreads();

    const int j = blockIdx.x / 784;
    const int i = (blockIdx.x % 784) * 256 + threadIdx.x;
    if (i >= g_cnt4[j]) return;
    const int lin = g_seglist[j * SEGCAP + i];

    float inv = 1.f / fmaxf(g_segcnt[lin], 1.f);
    float4 fk[16];
    {
        const float4* src = reinterpret_cast<const float4*>(
            g_segsum + (size_t)lin * 64);
        #pragma unroll
        for (int q = 0; q < 16; ++q) {
            float4 v = src[q];
            fk[q] = make_float4(v.x * inv, v.y * inv, v.z * inv, v.w * inv);
        }
    }
    float acc[32];
    #pragma unroll
    for (int c = 0; c < 32; ++c) acc[c] = sb[j * 32 + c];

    const float4* Wj = reinterpret_cast<const float4*>(sW) + (size_t)j * 64 * 8;
    #pragma unroll 4
    for (int k = 0; k < 64; ++k) {
        float4 v = fk[k >> 2];
        float xs = ((k & 3) == 0) ? v.x : ((k & 3) == 1) ? v.y
                   : ((k & 3) == 2) ? v.z : v.w;
        const float4* W = Wj + k * 8;
        #pragma unroll
        for (int c4 = 0; c4 < 8; ++c4) {
            float4 wv = W[c4];
            acc[c4 * 4 + 0] = fmaf(xs, wv.x, acc[c4 * 4 + 0]);
            acc[c4 * 4 + 1] = fmaf(xs, wv.y, acc[c4 * 4 + 1]);
            acc[c4 * 4 + 2] = fmaf(xs, wv.z, acc[c4 * 4 + 2]);
            acc[c4 * 4 + 3] = fmaf(xs, wv.w, acc[c4 * 4 + 3]);
        }
    }
    float4* dst = reinterpret_cast<float4*>(g_att + (size_t)(j * SEGCAP + i) * 32);
    #pragma unroll
    for (int c4 = 0; c4 < 8; ++c4)
        dst[c4] = make_float4(fmaxf(acc[c4 * 4 + 0], 0.f),
                              fmaxf(acc[c4 * 4 + 1], 0.f),
                              fmaxf(acc[c4 * 4 + 2], 0.f),
                              fmaxf(acc[c4 * 4 + 3], 0.f));
}

// ---------------- k2_pt: per-point chain (R2-k2b shape + featS/z phases) ---
// SMEM float offsets:
#define OFFP_FCW   0        // [32][32]     1024
#define OFFP_FCSW  1024     // [4][32][32]  4096
#define OFFP_FCSB  5120     // 128
#define OFFP_OUTW  5248     // [32][64]     2048
#define OFFP_LO1   7296     // [128][64]    8192
#define OFFP_LO2   15488    // [64][64]     4096
#define OFFP_LOB   19584    // 64
#define OFFP_X     19648    // scratch [64][256]  16384
#define K2PT_SMEM ((19648 + 16384) * 4)

__global__ void __launch_bounds__(256) k2_pt(
    const float* __restrict__ fcW, const float* __restrict__ fcsW,
    const float* __restrict__ fcsb, const float* __restrict__ outW,
    const float* __restrict__ lo1, const float* __restrict__ lo2,
    const float* __restrict__ lob)
{
    extern __shared__ float sm[];
    const int tid = threadIdx.x;

    for (int i = tid; i < 1024; i += 256) sm[OFFP_FCW + i]  = fcW[i];
    for (int i = tid; i < 4096; i += 256) sm[OFFP_FCSW + i] = fcsW[i];
    for (int i = tid; i < 128;  i += 256) sm[OFFP_FCSB + i] = fcsb[i];
    for (int i = tid; i < 2048; i += 256) sm[OFFP_OUTW + i] = outW[i];
    for (int i = tid; i < 8192; i += 256) sm[OFFP_LO1 + i]  = lo1[i];
    for (int i = tid; i < 4096; i += 256) sm[OFFP_LO2 + i]  = lo2[i];
    if (tid < 64) sm[OFFP_LOB + tid] = lob[tid];
    __syncthreads();

    const int n = blockIdx.x * 256 + tid;
    if (n >= NPTS) return;
    float* s_x = sm + OFFP_X;

    int idx4[4];
    #pragma unroll
    for (int j = 0; j < 4; ++j) idx4[j] = g_segidx[g_lin[n * 4 + j]];

    // ===== P1: featS = sum_j att_j ========================================
    float featS[32];
    #pragma unroll
    for (int c = 0; c < 32; ++c) featS[c] = 0.f;
    #pragma unroll 1
    for (int j = 0; j < 4; ++j) {
        const float4* sf = reinterpret_cast<const float4*>(
            g_att + (size_t)idx4[j] * 32);
        #pragma unroll
        for (int i = 0; i < 8; ++i) {
            float4 v = sf[i];
            featS[4 * i + 0] += v.x; featS[4 * i + 1] += v.y;
            featS[4 * i + 2] += v.z; featS[4 * i + 3] += v.w;
        }
    }

    // ===== P2: z = relu(featS @ fcW) -> scratch rows 32..63 ===============
    #pragma unroll
    for (int c = 0; c < 32; ++c) s_x[c * 256 + tid] = featS[c];
    {
        float acc[32];
        #pragma unroll
        for (int c = 0; c < 32; ++c) acc[c] = 0.f;
        #pragma unroll 1
        for (int k = 0; k < 32; ++k) {
            float fS = s_x[k * 256 + tid];
            #pragma unroll
            for (int c4 = 0; c4 < 8; ++c4) {
                float4 wv = reinterpret_cast<const float4*>(sm + OFFP_FCW)[k * 8 + c4];
                acc[c4 * 4 + 0] = fmaf(fS, wv.x, acc[c4 * 4 + 0]);
                acc[c4 * 4 + 1] = fmaf(fS, wv.y, acc[c4 * 4 + 1]);
                acc[c4 * 4 + 2] = fmaf(fS, wv.z, acc[c4 * 4 + 2]);
                acc[c4 * 4 + 3] = fmaf(fS, wv.w, acc[c4 * 4 + 3]);
            }
        }
        #pragma unroll
        for (int c = 0; c < 32; ++c) s_x[(32 + c) * 256 + tid] = fmaxf(acc[c], 0.f);
    }

    // ===== P3: fp = sum_j att_j * sigmoid(z @ fcsW_j + fcsb_j) ============
    float fp[32];
    #pragma unroll
    for (int c = 0; c < 32; ++c) fp[c] = 0.f;
    #pragma unroll 1
    for (int j = 0; j < 4; ++j) {
        float acc[32];
        #pragma unroll
        for (int c = 0; c < 32; ++c) acc[c] = sm[OFFP_FCSB + j * 32 + c];
        #pragma unroll 1
        for (int k = 0; k < 32; ++k) {
            float zk = s_x[(32 + k) * 256 + tid];
            #pragma unroll
            for (int c4 = 0; c4 < 8; ++c4) {
                float4 wv = reinterpret_cast<const float4*>(
                    sm + OFFP_FCSW)[(j * 32 + k) * 8 + c4];
                acc[c4 * 4 + 0] = fmaf(zk, wv.x, acc[c4 * 4 + 0]);
                acc[c4 * 4 + 1] = fmaf(zk, wv.y, acc[c4 * 4 + 1]);
                acc[c4 * 4 + 2] = fmaf(zk, wv.z, acc[c4 * 4 + 2]);
                acc[c4 * 4 + 3] = fmaf(zk, wv.w, acc[c4 * 4 + 3]);
            }
        }
        const float4* sfsrc = reinterpret_cast<const float4*>(
            g_att + (size_t)idx4[j] * 32);
        #pragma unroll
        for (int i = 0; i < 8; ++i) {
            float4 sv = sfsrc[i];
            float a0 = __fdividef(1.f, 1.f + __expf(-acc[4 * i + 0]));
            float a1 = __fdividef(1.f, 1.f + __expf(-acc[4 * i + 1]));
            float a2 = __fdividef(1.f, 1.f + __expf(-acc[4 * i + 2]));
            float a3 = __fdividef(1.f, 1.f + __expf(-acc[4 * i + 3]));
            fp[4 * i + 0] = fmaf(sv.x, a0, fp[4 * i + 0]);
            fp[4 * i + 1] = fmaf(sv.y, a1, fp[4 * i + 1]);
            fp[4 * i + 2] = fmaf(sv.z, a2, fp[4 * i + 2]);
            fp[4 * i + 3] = fmaf(sv.w, a3, fp[4 * i + 3]);
        }
    }

    // ===== P4: fused = fp @ outW ==========================================
    #pragma unroll
    for (int c = 0; c < 32; ++c) s_x[c * 256 + tid] = fp[c];
    float fused[64];
    #pragma unroll
    for (int c = 0; c < 64; ++c) fused[c] = 0.f;
    #pragma unroll 1
    for (int k = 0; k < 32; ++k) {
        float fpk = s_x[k * 256 + tid];
        #pragma unroll
        for (int c4 = 0; c4 < 16; ++c4) {
            float4 wv = reinterpret_cast<const float4*>(sm + OFFP_OUTW)[k * 16 + c4];
            fused[c4 * 4 + 0] = fmaf(fpk, wv.x, fused[c4 * 4 + 0]);
            fused[c4 * 4 + 1] = fmaf(fpk, wv.y, fused[c4 * 4 + 1]);
            fused[c4 * 4 + 2] = fmaf(fpk, wv.z, fused[c4 * 4 + 2]);
            fused[c4 * 4 + 3] = fmaf(fpk, wv.w, fused[c4 * 4 + 3]);
        }
    }

    // ===== P5: h = relu([reduced, fused] @ lo1) ===========================
    #pragma unroll
    for (int c = 0; c < 64; ++c) s_x[c * 256 + tid] = fused[c];
    float h[64];
    #pragma unroll
    for (int c = 0; c < 64; ++c) h[c] = 0.f;

    const float4* rsrc = reinterpret_cast<const float4*>(g_reduced + (size_t)n * 64);
    #pragma unroll 1
    for (int k4 = 0; k4 < 16; ++k4) {
        float4 r = rsrc[k4];
        #pragma unroll
        for (int kk = 0; kk < 4; ++kk) {
            float xk = (kk == 0) ? r.x : (kk == 1) ? r.y : (kk == 2) ? r.z : r.w;
            #pragma unroll
            for (int c4 = 0; c4 < 16; ++c4) {
                float4 wv = reinterpret_cast<const float4*>(
                    sm + OFFP_LO1)[(k4 * 4 + kk) * 16 + c4];
                h[c4 * 4 + 0] = fmaf(xk, wv.x, h[c4 * 4 + 0]);
                h[c4 * 4 + 1] = fmaf(xk, wv.y, h[c4 * 4 + 1]);
                h[c4 * 4 + 2] = fmaf(xk, wv.z, h[c4 * 4 + 2]);
                h[c4 * 4 + 3] = fmaf(xk, wv.w, h[c4 * 4 + 3]);
            }
        }
    }
    #pragma unroll 1
    for (int k = 0; k < 64; ++k) {
        float fk = s_x[k * 256 + tid];
        #pragma unroll
        for (int c4 = 0; c4 < 16; ++c4) {
            float4 wv = reinterpret_cast<const float4*>(
                sm + OFFP_LO1)[(64 + k) * 16 + c4];
            h[c4 * 4 + 0] = fmaf(fk, wv.x, h[c4 * 4 + 0]);
            h[c4 * 4 + 1] = fmaf(fk, wv.y, h[c4 * 4 + 1]);
            h[c4 * 4 + 2] = fmaf(fk, wv.z, h[c4 * 4 + 2]);
            h[c4 * 4 + 3] = fmaf(fk, wv.w, h[c4 * 4 + 3]);
        }
    }
    #pragma unroll
    for (int c = 0; c < 64; ++c) h[c] = fmaxf(h[c], 0.f);

    // ===== P6: proj = h @ lo2 + lob =======================================
    #pragma unroll
    for (int c = 0; c < 64; ++c) s_x[c * 256 + tid] = h[c];
    float p[64];
    #pragma unroll
    for (int c = 0; c < 64; ++c) p[c] = sm[OFFP_LOB + c];
    #pragma unroll 1
    for (int k = 0; k < 64; ++k) {
        float hk = s_x[k * 256 + tid];
        #pragma unroll
        for (int c4 = 0; c4 < 16; ++c4) {
            float4 wv = reinterpret_cast<const float4*>(sm + OFFP_LO2)[k * 16 + c4];
            p[c4 * 4 + 0] = fmaf(hk, wv.x, p[c4 * 4 + 0]);
            p[c4 * 4 + 1] = fmaf(hk, wv.y, p[c4 * 4 + 1]);
            p[c4 * 4 + 2] = fmaf(hk, wv.z, p[c4 * 4 + 2]);
            p[c4 * 4 + 3] = fmaf(hk, wv.w, p[c4 * 4 + 3]);
        }
    }
    float4* pdst = reinterpret_cast<float4*>(g_proj + (size_t)n * 64);
    #pragma unroll
    for (int c4 = 0; c4 < 16; ++c4)
        pdst[c4] = make_float4(p[c4 * 4 + 0], p[c4 * 4 + 1],
                               p[c4 * 4 + 2], p[c4 * 4 + 3]);
}

// ---------------- k3pre: sentinel-init touched tv segments + flags + lin2 --
__global__ void __launch_bounds__(256) k3pre(const int* __restrict__ bxyz,
                                             float* __restrict__ out)
{
    int w = (blockIdx.x * 256 + threadIdx.x) >> 5;
    int lane = threadIdx.x & 31;
    int4 b = reinterpret_cast<const int4*>(bxyz)[w];
    int lin2 = ((b.x * 16 + b.w) * 180 + b.z) * 240 + b.y;
    if (lane == 0) {
        g_flag[lin2] = 1;
        g_lin2[w] = lin2;
        out[(size_t)NPTS * 64 + (size_t)TVSEG * 64 + w] = (float)lin2;
    }
    if (lane < 16) {
        uint4 s = make_uint4(0xFFFFFFFFu, 0xFFFFFFFFu, 0xFFFFFFFFu, 0xFFFFFFFFu);
        reinterpret_cast<uint4*>(g_tv + (size_t)lin2 * 64)[lane] = s;
    }
}

// ---------------- k3: gather by inv + atomic segment-max -------------------
__device__ __forceinline__ void atomicMaxFloat(float* addr, float v)
{
    if (v >= 0.f) atomicMax((int*)addr, __float_as_int(v));
    else          atomicMin((unsigned int*)addr, __float_as_uint(v));
}

__global__ void __launch_bounds__(256) k3_scatter(const int* __restrict__ inv,
                                                  float* __restrict__ out)
{
    int idx = blockIdx.x * 256 + threadIdx.x;
    int n = idx >> 6, c = idx & 63;
    int src = inv[n];
    float v = g_proj[src * 64 + c];
    out[idx] = v;
    int lin2 = g_lin2[n];
    atomicMaxFloat(&g_tv[(size_t)lin2 * 64 + c], v);
}

// ---------------- k4: finalize tv -> out (flag-gated) ----------------------
__global__ void __launch_bounds__(256) k4_final(float* __restrict__ out)
{
    size_t idx = (size_t)blockIdx.x * 256 + threadIdx.x;   // float4 units
    size_t seg = idx >> 4;
    float4 v = make_float4(0.f, 0.f, 0.f, 0.f);
    if (g_flag[seg])
        v = reinterpret_cast<const float4*>(g_tv)[idx];
    reinterpret_cast<float4*>(out + (size_t)NPTS * 64)[idx] = v;
}

// ---------------- launch ---------------------------------------------------
extern "C" void kernel_launch(void* const* d_in, const int* in_sizes, int n_in,
                              void* d_out, int out_size)
{
    const float* input     = (const float*)d_in[0];
    const int*   coords    = (const int*)  d_in[1];
    const int*   inv       = (const int*)  d_in[2];
    const int*   bxyz      = (const int*)  d_in[3];
    const float* W_red     = (const float*)d_in[4];
    const float* b_red     = (const float*)d_in[5];
    const float* fc_list_W = (const float*)d_in[6];
    const float* fc_list_b = (const float*)d_in[7];
    const float* fcs_W     = (const float*)d_in[8];
    const float* fcs_b     = (const float*)d_in[9];
    const float* fc_W      = (const float*)d_in[10];
    const float* out_fc_W  = (const float*)d_in[11];
    const float* lo_W1     = (const float*)d_in[12];
    const float* lo_W2     = (const float*)d_in[13];
    const float* lo_b2     = (const float*)d_in[14];
    float* out = (float*)d_out;

    void* p;
    cudaGetSymbolAddress(&p, g_flag);
    cudaMemsetAsync(p, 0, TVSEG);
    cudaGetSymbolAddress(&p, g_segidx);
    cudaMemsetAsync(p, 0xFF, NSEG_TOTAL * sizeof(int));   // -1
    cudaGetSymbolAddress(&p, g_cnt4);
    cudaMemsetAsync(p, 0, 4 * sizeof(int));

    cudaFuncSetAttribute(k2_pt, cudaFuncAttributeMaxDynamicSharedMemorySize,
                         K2PT_SMEM);

    k0_zero<<<25000, 256>>>(coords);
    k1_reduce<<<25000, 256>>>(input, W_red, b_red);
    k2_seg<<<4 * 784, 256>>>(fc_list_W, fc_list_b);
    k2_pt<<<782, 256, K2PT_SMEM>>>(fc_W, fcs_W, fcs_b, out_fc_W,
                                   lo_W1, lo_W2, lo_b2);
    k3pre<<<25000, 256>>>(bxyz, out);
    k3_scatter<<<50000, 256>>>(inv, out);
    k4_final<<<86400, 256>>>(out);
}

// round 7
// speedup vs baseline: 1.1582x; 1.0143x over previous
#include <cuda_runtime.h>
#include <math.h>
#include <stdint.h>

#define NPTS 200000
#define TVSEG 1382400           // B*GZ2*GY2*GX2 = 2*16*180*240
#define NSEG_TOTAL 1634400      // 1382400 + 172800 + 57600 + 21600
#define SEGCAP 200704           // 784*256, >= max touched segs per scale

// ---------------- scratch (device globals; no allocation allowed) ----------
__device__ float g_reduced[NPTS * 64];                  // 51 MB
__device__ float g_segsum[(size_t)NSEG_TOTAL * 64];     // 418 MB (touched-only init)
__device__ float g_segcnt[NSEG_TOTAL];
__device__ int   g_lin[NPTS * 4];
__device__ int   g_segidx[NSEG_TOTAL];                  // lin -> att slot (init -1)
__device__ int   g_seglist[4 * SEGCAP];                 // compact touched lists
__device__ int   g_cnt4[4];
__device__ float g_att[(size_t)4 * SEGCAP * 32];        // 103 MB
__device__ float g_proj[NPTS * 64];
__device__ float g_tv[(size_t)TVSEG * 64];              // 354 MB (touched-only init)
__device__ int   g_lin2[NPTS];
__device__ unsigned char g_flag[TVSEG];

// ---------------- k0a: thread per (point,scale): lin + claim ticket --------
__global__ void __launch_bounds__(256) k0a_claim(const int* __restrict__ coords)
{
    int idx = blockIdx.x * 256 + threadIdx.x;    // 800000 exactly
    int n = idx >> 2, j = idx & 3;

    int4 c = reinterpret_cast<const int4*>(coords)[n];
    int ps = (j == 0) ? 2 : (j == 1) ? 4 : (j == 2) ? 6 : 8;
    int dx = (j == 0) ? 240 : (j == 1) ? 120 : (j == 2) ? 80 : 60;
    int dy = (j == 0) ? 180 : (j == 1) ? 90 : (j == 2) ? 60 : 45;
    int dz = (j == 0) ? 16 : (j == 1) ? 8 : (j == 2) ? 6 : 4;
    int off = (j == 0) ? 0 : (j == 1) ? 1382400 : (j == 2) ? 1555200 : 1612800;

    int lin = ((c.x * dx + c.y / ps) * dy + c.z / ps) * dz + c.w / ps + off;
    g_lin[idx] = lin;

    if (atomicCAS(&g_segidx[lin], -1, 0x40000000) == -1) {
        int t = atomicAdd(&g_cnt4[j], 1);
        g_seglist[j * SEGCAP + t] = lin;
        g_segidx[lin] = j * SEGCAP + t;
    }
}

// ---------------- k0b: zero ONLY claimed segments (list-driven) ------------
__global__ void __launch_bounds__(256) k0b_zero()
{
    int T = blockIdx.x * 256 + threadIdx.x;      // 8 threads per slot
    int slot = T >> 3, q = T & 7;
    int j = slot / SEGCAP, i = slot - j * SEGCAP;
    if (i >= g_cnt4[j]) return;
    int lin = g_seglist[slot];
    float4 z4 = make_float4(0.f, 0.f, 0.f, 0.f);
    float4* dst = reinterpret_cast<float4*>(g_segsum + (size_t)lin * 64) + q * 2;
    dst[0] = z4;
    dst[1] = z4;
    if (q == 0) g_segcnt[lin] = 0.f;
}

// ---------------- k1: reduced = relu(X@W_red + b) + atomic segment scatter -
__global__ void __launch_bounds__(256) k1_reduce(
    const float* __restrict__ input,
    const float* __restrict__ W_red, const float* __restrict__ b_red)
{
    __shared__ float sW[64 * 64];
    __shared__ float sb[64];
    for (int i = threadIdx.x; i < 64 * 64; i += 256) sW[i] = W_red[i];
    if (threadIdx.x < 64) sb[threadIdx.x] = b_red[threadIdx.x];
    __syncthreads();

    const int lane = threadIdx.x & 31;
    int w = (blockIdx.x * 256 + threadIdx.x) >> 5;

    float2 x2 = reinterpret_cast<const float2*>(input)[w * 32 + lane];
    float a0 = sb[2 * lane], a1 = sb[2 * lane + 1];
    #pragma unroll
    for (int k = 0; k < 64; ++k) {
        float xk = __shfl_sync(0xffffffffu, (k & 1) ? x2.y : x2.x, k >> 1);
        float2 w2 = reinterpret_cast<const float2*>(sW)[k * 32 + lane];
        a0 = fmaf(xk, w2.x, a0);
        a1 = fmaf(xk, w2.y, a1);
    }
    a0 = fmaxf(a0, 0.f); a1 = fmaxf(a1, 0.f);
    reinterpret_cast<float2*>(g_reduced)[w * 32 + lane] = make_float2(a0, a1);

    #pragma unroll
    for (int j = 0; j < 4; ++j) {
        int lin = g_lin[w * 4 + j];
        float* addr = g_segsum + (size_t)lin * 64 + 2 * lane;
        asm volatile("red.global.add.v2.f32 [%0], {%1, %2};"
                     :: "l"(addr), "f"(a0), "f"(a1) : "memory");
        if (lane == 0) atomicAdd(&g_segcnt[lin], 1.0f);
    }
}

// ---------------- k2_seg: per touched segment, att = relu(mean @ flW + b) --
__global__ void __launch_bounds__(256) k2_seg(
    const float* __restrict__ flW, const float* __restrict__ flb)
{
    __shared__ float sW[8192];
    __shared__ float sb[128];
    for (int i = threadIdx.x; i < 8192; i += 256) sW[i] = flW[i];
    if (threadIdx.x < 128) sb[threadIdx.x] = flb[threadIdx.x];
    __syncthreads();

    const int j = blockIdx.x / 784;
    const int i = (blockIdx.x % 784) * 256 + threadIdx.x;
    if (i >= g_cnt4[j]) return;
    const int lin = g_seglist[j * SEGCAP + i];

    float inv = 1.f / fmaxf(g_segcnt[lin], 1.f);
    float4 fk[16];
    {
        const float4* src = reinterpret_cast<const float4*>(
            g_segsum + (size_t)lin * 64);
        #pragma unroll
        for (int q = 0; q < 16; ++q) {
            float4 v = src[q];
            fk[q] = make_float4(v.x * inv, v.y * inv, v.z * inv, v.w * inv);
        }
    }
    float acc[32];
    #pragma unroll
    for (int c = 0; c < 32; ++c) acc[c] = sb[j * 32 + c];

    const float4* Wj = reinterpret_cast<const float4*>(sW) + (size_t)j * 64 * 8;
    #pragma unroll 4
    for (int k = 0; k < 64; ++k) {
        float4 v = fk[k >> 2];
        float xs = ((k & 3) == 0) ? v.x : ((k & 3) == 1) ? v.y
                   : ((k & 3) == 2) ? v.z : v.w;
        const float4* W = Wj + k * 8;
        #pragma unroll
        for (int c4 = 0; c4 < 8; ++c4) {
            float4 wv = W[c4];
            acc[c4 * 4 + 0] = fmaf(xs, wv.x, acc[c4 * 4 + 0]);
            acc[c4 * 4 + 1] = fmaf(xs, wv.y, acc[c4 * 4 + 1]);
            acc[c4 * 4 + 2] = fmaf(xs, wv.z, acc[c4 * 4 + 2]);
            acc[c4 * 4 + 3] = fmaf(xs, wv.w, acc[c4 * 4 + 3]);
        }
    }
    float4* dst = reinterpret_cast<float4*>(g_att + (size_t)(j * SEGCAP + i) * 32);
    #pragma unroll
    for (int c4 = 0; c4 < 8; ++c4)
        dst[c4] = make_float4(fmaxf(acc[c4 * 4 + 0], 0.f),
                              fmaxf(acc[c4 * 4 + 1], 0.f),
                              fmaxf(acc[c4 * 4 + 2], 0.f),
                              fmaxf(acc[c4 * 4 + 3], 0.f));
}

// ---------------- k2_pt: per-point chain, 512 thr/CTA for 16 warps/SM ------
#define K2T 512
// SMEM float offsets:
#define OFFP_FCW   0        // [32][32]     1024
#define OFFP_FCSW  1024     // [4][32][32]  4096
#define OFFP_FCSB  5120     // 128
#define OFFP_OUTW  5248     // [32][64]     2048
#define OFFP_LO1   7296     // [128][64]    8192
#define OFFP_LO2   15488    // [64][64]     4096
#define OFFP_LOB   19584    // 64
#define OFFP_X     19648    // scratch [64][512]  32768
#define K2PT_SMEM ((19648 + 64 * K2T) * 4)

__global__ void __launch_bounds__(K2T, 1) k2_pt(
    const float* __restrict__ fcW, const float* __restrict__ fcsW,
    const float* __restrict__ fcsb, const float* __restrict__ outW,
    const float* __restrict__ lo1, const float* __restrict__ lo2,
    const float* __restrict__ lob)
{
    extern __shared__ float sm[];
    const int tid = threadIdx.x;

    for (int i = tid; i < 1024; i += K2T) sm[OFFP_FCW + i]  = fcW[i];
    for (int i = tid; i < 4096; i += K2T) sm[OFFP_FCSW + i] = fcsW[i];
    for (int i = tid; i < 128;  i += K2T) sm[OFFP_FCSB + i] = fcsb[i];
    for (int i = tid; i < 2048; i += K2T) sm[OFFP_OUTW + i] = outW[i];
    for (int i = tid; i < 8192; i += K2T) sm[OFFP_LO1 + i]  = lo1[i];
    for (int i = tid; i < 4096; i += K2T) sm[OFFP_LO2 + i]  = lo2[i];
    if (tid < 64) sm[OFFP_LOB + tid] = lob[tid];
    __syncthreads();

    const int n = blockIdx.x * K2T + tid;
    if (n >= NPTS) return;
    float* s_x = sm + OFFP_X;

    int idx4[4];
    #pragma unroll
    for (int j = 0; j < 4; ++j) idx4[j] = g_segidx[g_lin[n * 4 + j]];

    // ===== P1: featS = sum_j att_j ========================================
    float featS[32];
    #pragma unroll
    for (int c = 0; c < 32; ++c) featS[c] = 0.f;
    #pragma unroll 1
    for (int j = 0; j < 4; ++j) {
        const float4* sf = reinterpret_cast<const float4*>(
            g_att + (size_t)idx4[j] * 32);
        #pragma unroll
        for (int i = 0; i < 8; ++i) {
            float4 v = sf[i];
            featS[4 * i + 0] += v.x; featS[4 * i + 1] += v.y;
            featS[4 * i + 2] += v.z; featS[4 * i + 3] += v.w;
        }
    }

    // ===== P2: z = relu(featS @ fcW) -> scratch rows 32..63 ===============
    #pragma unroll
    for (int c = 0; c < 32; ++c) s_x[c * K2T + tid] = featS[c];
    {
        float acc[32];
        #pragma unroll
        for (int c = 0; c < 32; ++c) acc[c] = 0.f;
        #pragma unroll 1
        for (int k = 0; k < 32; ++k) {
            float fS = s_x[k * K2T + tid];
            #pragma unroll
            for (int c4 = 0; c4 < 8; ++c4) {
                float4 wv = reinterpret_cast<const float4*>(sm + OFFP_FCW)[k * 8 + c4];
                acc[c4 * 4 + 0] = fmaf(fS, wv.x, acc[c4 * 4 + 0]);
                acc[c4 * 4 + 1] = fmaf(fS, wv.y, acc[c4 * 4 + 1]);
                acc[c4 * 4 + 2] = fmaf(fS, wv.z, acc[c4 * 4 + 2]);
                acc[c4 * 4 + 3] = fmaf(fS, wv.w, acc[c4 * 4 + 3]);
            }
        }
        #pragma unroll
        for (int c = 0; c < 32; ++c) s_x[(32 + c) * K2T + tid] = fmaxf(acc[c], 0.f);
    }

    // ===== P3: fp = sum_j att_j * sigmoid(z @ fcsW_j + fcsb_j) ============
    float fp[32];
    #pragma unroll
    for (int c = 0; c < 32; ++c) fp[c] = 0.f;
    #pragma unroll 1
    for (int j = 0; j < 4; ++j) {
        float acc[32];
        #pragma unroll
        for (int c = 0; c < 32; ++c) acc[c] = sm[OFFP_FCSB + j * 32 + c];
        #pragma unroll 1
        for (int k = 0; k < 32; ++k) {
            float zk = s_x[(32 + k) * K2T + tid];
            #pragma unroll
            for (int c4 = 0; c4 < 8; ++c4) {
                float4 wv = reinterpret_cast<const float4*>(
                    sm + OFFP_FCSW)[(j * 32 + k) * 8 + c4];
                acc[c4 * 4 + 0] = fmaf(zk, wv.x, acc[c4 * 4 + 0]);
                acc[c4 * 4 + 1] = fmaf(zk, wv.y, acc[c4 * 4 + 1]);
                acc[c4 * 4 + 2] = fmaf(zk, wv.z, acc[c4 * 4 + 2]);
                acc[c4 * 4 + 3] = fmaf(zk, wv.w, acc[c4 * 4 + 3]);
            }
        }
        const float4* sfsrc = reinterpret_cast<const float4*>(
            g_att + (size_t)idx4[j] * 32);
        #pragma unroll
        for (int i = 0; i < 8; ++i) {
            float4 sv = sfsrc[i];
            float a0 = __fdividef(1.f, 1.f + __expf(-acc[4 * i + 0]));
            float a1 = __fdividef(1.f, 1.f + __expf(-acc[4 * i + 1]));
            float a2 = __fdividef(1.f, 1.f + __expf(-acc[4 * i + 2]));
            float a3 = __fdividef(1.f, 1.f + __expf(-acc[4 * i + 3]));
            fp[4 * i + 0] = fmaf(sv.x, a0, fp[4 * i + 0]);
            fp[4 * i + 1] = fmaf(sv.y, a1, fp[4 * i + 1]);
            fp[4 * i + 2] = fmaf(sv.z, a2, fp[4 * i + 2]);
            fp[4 * i + 3] = fmaf(sv.w, a3, fp[4 * i + 3]);
        }
    }

    // ===== P4: fused = fp @ outW ==========================================
    #pragma unroll
    for (int c = 0; c < 32; ++c) s_x[c * K2T + tid] = fp[c];
    float fused[64];
    #pragma unroll
    for (int c = 0; c < 64; ++c) fused[c] = 0.f;
    #pragma unroll 1
    for (int k = 0; k < 32; ++k) {
        float fpk = s_x[k * K2T + tid];
        #pragma unroll
        for (int c4 = 0; c4 < 16; ++c4) {
            float4 wv = reinterpret_cast<const float4*>(sm + OFFP_OUTW)[k * 16 + c4];
            fused[c4 * 4 + 0] = fmaf(fpk, wv.x, fused[c4 * 4 + 0]);
            fused[c4 * 4 + 1] = fmaf(fpk, wv.y, fused[c4 * 4 + 1]);
            fused[c4 * 4 + 2] = fmaf(fpk, wv.z, fused[c4 * 4 + 2]);
            fused[c4 * 4 + 3] = fmaf(fpk, wv.w, fused[c4 * 4 + 3]);
        }
    }

    // ===== P5: h = relu([reduced, fused] @ lo1) ===========================
    #pragma unroll
    for (int c = 0; c < 64; ++c) s_x[c * K2T + tid] = fused[c];
    float h[64];
    #pragma unroll
    for (int c = 0; c < 64; ++c) h[c] = 0.f;

    const float4* rsrc = reinterpret_cast<const float4*>(g_reduced + (size_t)n * 64);
    #pragma unroll 1
    for (int k4 = 0; k4 < 16; ++k4) {
        float4 r = rsrc[k4];
        #pragma unroll
        for (int kk = 0; kk < 4; ++kk) {
            float xk = (kk == 0) ? r.x : (kk == 1) ? r.y : (kk == 2) ? r.z : r.w;
            #pragma unroll
            for (int c4 = 0; c4 < 16; ++c4) {
                float4 wv = reinterpret_cast<const float4*>(
                    sm + OFFP_LO1)[(k4 * 4 + kk) * 16 + c4];
                h[c4 * 4 + 0] = fmaf(xk, wv.x, h[c4 * 4 + 0]);
                h[c4 * 4 + 1] = fmaf(xk, wv.y, h[c4 * 4 + 1]);
                h[c4 * 4 + 2] = fmaf(xk, wv.z, h[c4 * 4 + 2]);
                h[c4 * 4 + 3] = fmaf(xk, wv.w, h[c4 * 4 + 3]);
            }
        }
    }
    #pragma unroll 1
    for (int k = 0; k < 64; ++k) {
        float fk = s_x[k * K2T + tid];
        #pragma unroll
        for (int c4 = 0; c4 < 16; ++c4) {
            float4 wv = reinterpret_cast<const float4*>(
                sm + OFFP_LO1)[(64 + k) * 16 + c4];
            h[c4 * 4 + 0] = fmaf(fk, wv.x, h[c4 * 4 + 0]);
            h[c4 * 4 + 1] = fmaf(fk, wv.y, h[c4 * 4 + 1]);
            h[c4 * 4 + 2] = fmaf(fk, wv.z, h[c4 * 4 + 2]);
            h[c4 * 4 + 3] = fmaf(fk, wv.w, h[c4 * 4 + 3]);
        }
    }
    #pragma unroll
    for (int c = 0; c < 64; ++c) h[c] = fmaxf(h[c], 0.f);

    // ===== P6: proj = h @ lo2 + lob =======================================
    #pragma unroll
    for (int c = 0; c < 64; ++c) s_x[c * K2T + tid] = h[c];
    float p[64];
    #pragma unroll
    for (int c = 0; c < 64; ++c) p[c] = sm[OFFP_LOB + c];
    #pragma unroll 1
    for (int k = 0; k < 64; ++k) {
        float hk = s_x[k * K2T + tid];
        #pragma unroll
        for (int c4 = 0; c4 < 16; ++c4) {
            float4 wv = reinterpret_cast<const float4*>(sm + OFFP_LO2)[k * 16 + c4];
            p[c4 * 4 + 0] = fmaf(hk, wv.x, p[c4 * 4 + 0]);
            p[c4 * 4 + 1] = fmaf(hk, wv.y, p[c4 * 4 + 1]);
            p[c4 * 4 + 2] = fmaf(hk, wv.z, p[c4 * 4 + 2]);
            p[c4 * 4 + 3] = fmaf(hk, wv.w, p[c4 * 4 + 3]);
        }
    }
    float4* pdst = reinterpret_cast<float4*>(g_proj + (size_t)n * 64);
    #pragma unroll
    for (int c4 = 0; c4 < 16; ++c4)
        pdst[c4] = make_float4(p[c4 * 4 + 0], p[c4 * 4 + 1],
                               p[c4 * 4 + 2], p[c4 * 4 + 3]);
}

// ---------------- k3pre: sentinel-init touched tv segments + flags + lin2 --
__global__ void __launch_bounds__(256) k3pre(const int* __restrict__ bxyz,
                                             float* __restrict__ out)
{
    int w = (blockIdx.x * 256 + threadIdx.x) >> 5;
    int lane = threadIdx.x & 31;
    int4 b = reinterpret_cast<const int4*>(bxyz)[w];
    int lin2 = ((b.x * 16 + b.w) * 180 + b.z) * 240 + b.y;
    if (lane == 0) {
        g_flag[lin2] = 1;
        g_lin2[w] = lin2;
        out[(size_t)NPTS * 64 + (size_t)TVSEG * 64 + w] = (float)lin2;
    }
    if (lane < 16) {
        uint4 s = make_uint4(0xFFFFFFFFu, 0xFFFFFFFFu, 0xFFFFFFFFu, 0xFFFFFFFFu);
        reinterpret_cast<uint4*>(g_tv + (size_t)lin2 * 64)[lane] = s;
    }
}

// ---------------- k3: gather by inv + atomic segment-max -------------------
__device__ __forceinline__ void atomicMaxFloat(float* addr, float v)
{
    if (v >= 0.f) atomicMax((int*)addr, __float_as_int(v));
    else          atomicMin((unsigned int*)addr, __float_as_uint(v));
}

__global__ void __launch_bounds__(256) k3_scatter(const int* __restrict__ inv,
                                                  float* __restrict__ out)
{
    int idx = blockIdx.x * 256 + threadIdx.x;
    int n = idx >> 6, c = idx & 63;
    int src = inv[n];
    float v = g_proj[src * 64 + c];
    out[idx] = v;
    int lin2 = g_lin2[n];
    atomicMaxFloat(&g_tv[(size_t)lin2 * 64 + c], v);
}

// ---------------- k4: finalize tv -> out (flag-gated) ----------------------
__global__ void __launch_bounds__(256) k4_final(float* __restrict__ out)
{
    size_t idx = (size_t)blockIdx.x * 256 + threadIdx.x;   // float4 units
    size_t seg = idx >> 4;
    float4 v = make_float4(0.f, 0.f, 0.f, 0.f);
    if (g_flag[seg])
        v = reinterpret_cast<const float4*>(g_tv)[idx];
    reinterpret_cast<float4*>(out + (size_t)NPTS * 64)[idx] = v;
}

// ---------------- launch ---------------------------------------------------
extern "C" void kernel_launch(void* const* d_in, const int* in_sizes, int n_in,
                              void* d_out, int out_size)
{
    const float* input     = (const float*)d_in[0];
    const int*   coords    = (const int*)  d_in[1];
    const int*   inv       = (const int*)  d_in[2];
    const int*   bxyz      = (const int*)  d_in[3];
    const float* W_red     = (const float*)d_in[4];
    const float* b_red     = (const float*)d_in[5];
    const float* fc_list_W = (const float*)d_in[6];
    const float* fc_list_b = (const float*)d_in[7];
    const float* fcs_W     = (const float*)d_in[8];
    const float* fcs_b     = (const float*)d_in[9];
    const float* fc_W      = (const float*)d_in[10];
    const float* out_fc_W  = (const float*)d_in[11];
    const float* lo_W1     = (const float*)d_in[12];
    const float* lo_W2     = (const float*)d_in[13];
    const float* lo_b2     = (const float*)d_in[14];
    float* out = (float*)d_out;

    void* p;
    cudaGetSymbolAddress(&p, g_flag);
    cudaMemsetAsync(p, 0, TVSEG);
    cudaGetSymbolAddress(&p, g_segidx);
    cudaMemsetAsync(p, 0xFF, NSEG_TOTAL * sizeof(int));   // -1
    cudaGetSymbolAddress(&p, g_cnt4);
    cudaMemsetAsync(p, 0, 4 * sizeof(int));

    cudaFuncSetAttribute(k2_pt, cudaFuncAttributeMaxDynamicSharedMemorySize,
                         K2PT_SMEM);

    k0a_claim<<<3125, 256>>>(coords);                       // 800k threads
    k0b_zero<<<(4 * SEGCAP * 8) / 256, 256>>>();            // 8 thr/slot
    k1_reduce<<<25000, 256>>>(input, W_red, b_red);
    k2_seg<<<4 * 784, 256>>>(fc_list_W, fc_list_b);
    k2_pt<<<(NPTS + K2T - 1) / K2T, K2T, K2PT_SMEM>>>(fc_W, fcs_W, fcs_b,
                                                      out_fc_W, lo_W1, lo_W2,
                                                      lo_b2);
    k3pre<<<25000, 256>>>(bxyz, out);
    k3_scatter<<<50000, 256>>>(inv, out);
    k4_final<<<86400, 256>>>(out);
}

// round 8
// speedup vs baseline: 1.1915x; 1.0287x over previous
#include <cuda_runtime.h>
#include <math.h>
#include <stdint.h>

#define NPTS 200000
#define TVSEG 1382400           // B*GZ2*GY2*GX2 = 2*16*180*240
#define NSEG_TOTAL 1634400      // 1382400 + 172800 + 57600 + 21600
#define SEGCAP 200704           // 784*256, >= max touched segs per scale

typedef unsigned long long u64;

// packed fp32x2 (Blackwell): d = a*b + d on two fp32 lanes
#define FFMA2(acc, a, b) \
    asm("fma.rn.f32x2 %0, %1, %2, %0;" : "+l"(acc) : "l"(a), "l"(b))
#define PACK2(d, f) \
    asm("mov.b64 %0, {%1, %1};" : "=l"(d) : "f"(f))
#define PACKLH(d, lo, hi) \
    asm("mov.b64 %0, {%1, %2};" : "=l"(d) : "f"(lo), "f"(hi))
#define UNPK(lo, hi, u) \
    asm("mov.b64 {%0, %1}, %2;" : "=f"(lo), "=f"(hi) : "l"(u))

// ---------------- scratch (device globals; no allocation allowed) ----------
__device__ float g_reduced[NPTS * 64];                  // 51 MB
__device__ float g_segsum[(size_t)NSEG_TOTAL * 64];     // 418 MB (touched-only init)
__device__ float g_segcnt[NSEG_TOTAL];
__device__ int   g_lin[NPTS * 4];
__device__ int   g_segidx[NSEG_TOTAL];                  // lin -> att slot (init -1)
__device__ int   g_seglist[4 * SEGCAP];                 // compact touched lists
__device__ int   g_cnt4[4];
__device__ float g_att[(size_t)4 * SEGCAP * 32];        // 103 MB
__device__ float g_proj[NPTS * 64];
__device__ float g_tv[(size_t)TVSEG * 64];              // 354 MB (touched-only init)
__device__ int   g_lin2[NPTS];
__device__ unsigned char g_flag[TVSEG];

// ---------------- k0a: thread per (point,scale): lin + claim ticket --------
__global__ void __launch_bounds__(256) k0a_claim(const int* __restrict__ coords)
{
    int idx = blockIdx.x * 256 + threadIdx.x;    // 800000 exactly
    int n = idx >> 2, j = idx & 3;

    int4 c = reinterpret_cast<const int4*>(coords)[n];
    int ps = (j == 0) ? 2 : (j == 1) ? 4 : (j == 2) ? 6 : 8;
    int dx = (j == 0) ? 240 : (j == 1) ? 120 : (j == 2) ? 80 : 60;
    int dy = (j == 0) ? 180 : (j == 1) ? 90 : (j == 2) ? 60 : 45;
    int dz = (j == 0) ? 16 : (j == 1) ? 8 : (j == 2) ? 6 : 4;
    int off = (j == 0) ? 0 : (j == 1) ? 1382400 : (j == 2) ? 1555200 : 1612800;

    int lin = ((c.x * dx + c.y / ps) * dy + c.z / ps) * dz + c.w / ps + off;
    g_lin[idx] = lin;

    if (atomicCAS(&g_segidx[lin], -1, 0x40000000) == -1) {
        int t = atomicAdd(&g_cnt4[j], 1);
        g_seglist[j * SEGCAP + t] = lin;
        g_segidx[lin] = j * SEGCAP + t;
    }
}

// ---------------- k0b: zero ONLY claimed segments (list-driven) ------------
__global__ void __launch_bounds__(256) k0b_zero()
{
    int T = blockIdx.x * 256 + threadIdx.x;      // 8 threads per slot
    int slot = T >> 3, q = T & 7;
    int j = slot / SEGCAP, i = slot - j * SEGCAP;
    if (i >= g_cnt4[j]) return;
    int lin = g_seglist[slot];
    float4 z4 = make_float4(0.f, 0.f, 0.f, 0.f);
    float4* dst = reinterpret_cast<float4*>(g_segsum + (size_t)lin * 64) + q * 2;
    dst[0] = z4;
    dst[1] = z4;
    if (q == 0) g_segcnt[lin] = 0.f;
}

// ---------------- k1: reduced = relu(X@W_red + b) + atomic segment scatter -
__global__ void __launch_bounds__(256) k1_reduce(
    const float* __restrict__ input,
    const float* __restrict__ W_red, const float* __restrict__ b_red)
{
    __shared__ float sW[64 * 64];
    __shared__ float sb[64];
    for (int i = threadIdx.x; i < 64 * 64; i += 256) sW[i] = W_red[i];
    if (threadIdx.x < 64) sb[threadIdx.x] = b_red[threadIdx.x];
    __syncthreads();

    const int lane = threadIdx.x & 31;
    int w = (blockIdx.x * 256 + threadIdx.x) >> 5;

    float2 x2 = reinterpret_cast<const float2*>(input)[w * 32 + lane];
    float a0 = sb[2 * lane], a1 = sb[2 * lane + 1];
    #pragma unroll
    for (int k = 0; k < 64; ++k) {
        float xk = __shfl_sync(0xffffffffu, (k & 1) ? x2.y : x2.x, k >> 1);
        float2 w2 = reinterpret_cast<const float2*>(sW)[k * 32 + lane];
        a0 = fmaf(xk, w2.x, a0);
        a1 = fmaf(xk, w2.y, a1);
    }
    a0 = fmaxf(a0, 0.f); a1 = fmaxf(a1, 0.f);
    reinterpret_cast<float2*>(g_reduced)[w * 32 + lane] = make_float2(a0, a1);

    #pragma unroll
    for (int j = 0; j < 4; ++j) {
        int lin = g_lin[w * 4 + j];
        float* addr = g_segsum + (size_t)lin * 64 + 2 * lane;
        asm volatile("red.global.add.v2.f32 [%0], {%1, %2};"
                     :: "l"(addr), "f"(a0), "f"(a1) : "memory");
        if (lane == 0) atomicAdd(&g_segcnt[lin], 1.0f);
    }
}

// ---------------- k2_seg: per touched segment, att = relu(mean @ flW + b) --
__global__ void __launch_bounds__(256) k2_seg(
    const float* __restrict__ flW, const float* __restrict__ flb)
{
    __shared__ __align__(16) float sW[8192];
    __shared__ __align__(16) float sb[128];
    for (int i = threadIdx.x; i < 8192; i += 256) sW[i] = flW[i];
    if (threadIdx.x < 128) sb[threadIdx.x] = flb[threadIdx.x];
    __syncthreads();

    const int j = blockIdx.x / 784;
    const int i = (blockIdx.x % 784) * 256 + threadIdx.x;
    if (i >= g_cnt4[j]) return;
    const int lin = g_seglist[j * SEGCAP + i];

    float inv = 1.f / fmaxf(g_segcnt[lin], 1.f);

    u64 acc[16];
    {
        const u64* bp = reinterpret_cast<const u64*>(sb + j * 32);
        #pragma unroll
        for (int q = 0; q < 16; ++q) acc[q] = bp[q];
    }
    const ulonglong2* Wj = reinterpret_cast<const ulonglong2*>(sW)
                           + (size_t)j * 64 * 8;
    const float4* src = reinterpret_cast<const float4*>(g_segsum + (size_t)lin * 64);

    #pragma unroll 1
    for (int kc = 0; kc < 4; ++kc) {
        float4 fk4[4];
        #pragma unroll
        for (int q = 0; q < 4; ++q) fk4[q] = src[kc * 4 + q];
        #pragma unroll
        for (int k = 0; k < 16; ++k) {
            float4 v = fk4[k >> 2];
            float xs = ((k & 3) == 0) ? v.x : ((k & 3) == 1) ? v.y
                       : ((k & 3) == 2) ? v.z : v.w;
            xs *= inv;
            u64 xp; PACK2(xp, xs);
            const ulonglong2* W = Wj + (kc * 16 + k) * 8;
            #pragma unroll
            for (int q = 0; q < 8; ++q) {
                ulonglong2 wv = W[q];
                FFMA2(acc[2 * q],     xp, wv.x);
                FFMA2(acc[2 * q + 1], xp, wv.y);
            }
        }
    }
    float4* dst = reinterpret_cast<float4*>(g_att + (size_t)(j * SEGCAP + i) * 32);
    #pragma unroll
    for (int q = 0; q < 8; ++q) {
        float l0, h0, l1, h1;
        UNPK(l0, h0, acc[2 * q]);
        UNPK(l1, h1, acc[2 * q + 1]);
        dst[q] = make_float4(fmaxf(l0, 0.f), fmaxf(h0, 0.f),
                             fmaxf(l1, 0.f), fmaxf(h1, 0.f));
    }
}

// ---------------- k2_pt: per-point chain, f32x2 channel-packed -------------
#define K2T 256
// SMEM float offsets:
#define OFFP_FCW   0        // [32][32]     1024
#define OFFP_FCSW  1024     // [4][32][32]  4096
#define OFFP_FCSB  5120     // 128
#define OFFP_OUTW  5248     // [32][64]     2048
#define OFFP_LO1   7296     // [128][64]    8192
#define OFFP_LO2   15488    // [64][64]     4096
#define OFFP_LOB   19584    // 64
#define OFFP_X     19648    // scratch [32][256]  8192
#define K2PT_SMEM ((19648 + 32 * K2T) * 4)

__global__ void __launch_bounds__(K2T, 2) k2_pt(
    const float* __restrict__ fcW, const float* __restrict__ fcsW,
    const float* __restrict__ fcsb, const float* __restrict__ outW,
    const float* __restrict__ lo1, const float* __restrict__ lo2,
    const float* __restrict__ lob)
{
    extern __shared__ float sm[];
    const int tid = threadIdx.x;

    for (int i = tid; i < 1024; i += K2T) sm[OFFP_FCW + i]  = fcW[i];
    for (int i = tid; i < 4096; i += K2T) sm[OFFP_FCSW + i] = fcsW[i];
    for (int i = tid; i < 128;  i += K2T) sm[OFFP_FCSB + i] = fcsb[i];
    for (int i = tid; i < 2048; i += K2T) sm[OFFP_OUTW + i] = outW[i];
    for (int i = tid; i < 8192; i += K2T) sm[OFFP_LO1 + i]  = lo1[i];
    for (int i = tid; i < 4096; i += K2T) sm[OFFP_LO2 + i]  = lo2[i];
    if (tid < 64) sm[OFFP_LOB + tid] = lob[tid];
    __syncthreads();

    const int n = blockIdx.x * K2T + tid;
    if (n >= NPTS) return;
    float* s_x = sm + OFFP_X;

    int idx4[4];
    #pragma unroll
    for (int j = 0; j < 4; ++j) idx4[j] = g_segidx[g_lin[n * 4 + j]];

    // ===== P1: featS = sum_j att_j (regs) =================================
    float featS[32];
    #pragma unroll
    for (int c = 0; c < 32; ++c) featS[c] = 0.f;
    #pragma unroll 1
    for (int j = 0; j < 4; ++j) {
        const float4* sf = reinterpret_cast<const float4*>(
            g_att + (size_t)idx4[j] * 32);
        #pragma unroll
        for (int i = 0; i < 8; ++i) {
            float4 v = sf[i];
            featS[4 * i + 0] += v.x; featS[4 * i + 1] += v.y;
            featS[4 * i + 2] += v.z; featS[4 * i + 3] += v.w;
        }
    }

    // ===== P2: z = relu(featS @ fcW), z kept packed (u64 pairs) ===========
    u64 zp[16];
    {
        #pragma unroll
        for (int i = 0; i < 16; ++i) zp[i] = 0ull;
        const ulonglong2* Wf = reinterpret_cast<const ulonglong2*>(sm + OFFP_FCW);
        #pragma unroll
        for (int k = 0; k < 32; ++k) {
            u64 xp; PACK2(xp, featS[k]);
            const ulonglong2* W = Wf + k * 8;
            #pragma unroll
            for (int i = 0; i < 8; ++i) {
                ulonglong2 wv = W[i];
                FFMA2(zp[2 * i],     xp, wv.x);
                FFMA2(zp[2 * i + 1], xp, wv.y);
            }
        }
        #pragma unroll
        for (int i = 0; i < 16; ++i) {
            float lo, hi; UNPK(lo, hi, zp[i]);
            lo = fmaxf(lo, 0.f); hi = fmaxf(hi, 0.f);
            PACKLH(zp[i], lo, hi);
        }
    }

    // ===== P3: fp = sum_j att_j * sigmoid(z @ fcsW_j + fcsb_j) ============
    float fp[32];
    #pragma unroll
    for (int c = 0; c < 32; ++c) fp[c] = 0.f;
    #pragma unroll 1
    for (int j = 0; j < 4; ++j) {
        u64 acc[16];
        {
            const u64* bp = reinterpret_cast<const u64*>(sm + OFFP_FCSB + j * 32);
            #pragma unroll
            for (int i = 0; i < 16; ++i) acc[i] = bp[i];
        }
        const ulonglong2* Wj = reinterpret_cast<const ulonglong2*>(sm + OFFP_FCSW)
                               + (size_t)j * 32 * 8;
        #pragma unroll
        for (int kp = 0; kp < 16; ++kp) {
            float zl, zh; UNPK(zl, zh, zp[kp]);
            u64 xp0; PACK2(xp0, zl);
            const ulonglong2* W = Wj + (2 * kp) * 8;
            #pragma unroll
            for (int i = 0; i < 8; ++i) {
                ulonglong2 wv = W[i];
                FFMA2(acc[2 * i],     xp0, wv.x);
                FFMA2(acc[2 * i + 1], xp0, wv.y);
            }
            u64 xp1; PACK2(xp1, zh);
            W = Wj + (2 * kp + 1) * 8;
            #pragma unroll
            for (int i = 0; i < 8; ++i) {
                ulonglong2 wv = W[i];
                FFMA2(acc[2 * i],     xp1, wv.x);
                FFMA2(acc[2 * i + 1], xp1, wv.y);
            }
        }
        const float4* sfsrc = reinterpret_cast<const float4*>(
            g_att + (size_t)idx4[j] * 32);
        #pragma unroll
        for (int i = 0; i < 8; ++i) {
            float4 sv = sfsrc[i];
            float l0, h0, l1, h1;
            UNPK(l0, h0, acc[2 * i]);
            UNPK(l1, h1, acc[2 * i + 1]);
            float a0 = __fdividef(1.f, 1.f + __expf(-l0));
            float a1 = __fdividef(1.f, 1.f + __expf(-h0));
            float a2 = __fdividef(1.f, 1.f + __expf(-l1));
            float a3 = __fdividef(1.f, 1.f + __expf(-h1));
            fp[4 * i + 0] = fmaf(sv.x, a0, fp[4 * i + 0]);
            fp[4 * i + 1] = fmaf(sv.y, a1, fp[4 * i + 1]);
            fp[4 * i + 2] = fmaf(sv.z, a2, fp[4 * i + 2]);
            fp[4 * i + 3] = fmaf(sv.w, a3, fp[4 * i + 3]);
        }
    }

    // ===== P4: fused = fp @ outW (packed); low half -> scratch ============
    u64 facc[32];
    {
        #pragma unroll
        for (int i = 0; i < 32; ++i) facc[i] = 0ull;
        const ulonglong2* Wo = reinterpret_cast<const ulonglong2*>(sm + OFFP_OUTW);
        #pragma unroll
        for (int k = 0; k < 32; ++k) {
            u64 xp; PACK2(xp, fp[k]);
            const ulonglong2* W = Wo + k * 16;
            #pragma unroll
            for (int i = 0; i < 16; ++i) {
                ulonglong2 wv = W[i];
                FFMA2(facc[2 * i],     xp, wv.x);
                FFMA2(facc[2 * i + 1], xp, wv.y);
            }
        }
        // stage fused channels 0..31 (facc[0..15]) to scratch rows 0..31
        #pragma unroll
        for (int i = 0; i < 16; ++i) {
            float lo, hi; UNPK(lo, hi, facc[i]);
            s_x[(2 * i) * K2T + tid]     = lo;
            s_x[(2 * i + 1) * K2T + tid] = hi;
        }
    }

    // ===== P5: h = relu([reduced, fused] @ lo1) (packed accs) =============
    float h[64];
    {
        u64 hacc[32];
        #pragma unroll
        for (int i = 0; i < 32; ++i) hacc[i] = 0ull;
        const ulonglong2* Wl = reinterpret_cast<const ulonglong2*>(sm + OFFP_LO1);
        const float4* rsrc = reinterpret_cast<const float4*>(
            g_reduced + (size_t)n * 64);
        // (a) reduced, k = 0..63
        #pragma unroll 1
        for (int k4 = 0; k4 < 16; ++k4) {
            float4 r = rsrc[k4];
            #pragma unroll
            for (int kk = 0; kk < 4; ++kk) {
                float xs = (kk == 0) ? r.x : (kk == 1) ? r.y : (kk == 2) ? r.z : r.w;
                u64 xp; PACK2(xp, xs);
                const ulonglong2* W = Wl + (k4 * 4 + kk) * 16;
                #pragma unroll
                for (int i = 0; i < 16; ++i) {
                    ulonglong2 wv = W[i];
                    FFMA2(hacc[2 * i],     xp, wv.x);
                    FFMA2(hacc[2 * i + 1], xp, wv.y);
                }
            }
        }
        // (b) fused low from scratch, k = 64..95
        #pragma unroll 1
        for (int k = 0; k < 32; ++k) {
            float xs = s_x[k * K2T + tid];
            u64 xp; PACK2(xp, xs);
            const ulonglong2* W = Wl + (64 + k) * 16;
            #pragma unroll
            for (int i = 0; i < 16; ++i) {
                ulonglong2 wv = W[i];
                FFMA2(hacc[2 * i],     xp, wv.x);
                FFMA2(hacc[2 * i + 1], xp, wv.y);
            }
        }
        // (c) fused high from regs, k = 96..127
        #pragma unroll
        for (int kp = 0; kp < 16; ++kp) {
            float f0, f1; UNPK(f0, f1, facc[16 + kp]);
            u64 xp0; PACK2(xp0, f0);
            const ulonglong2* W = Wl + (96 + 2 * kp) * 16;
            #pragma unroll
            for (int i = 0; i < 16; ++i) {
                ulonglong2 wv = W[i];
                FFMA2(hacc[2 * i],     xp0, wv.x);
                FFMA2(hacc[2 * i + 1], xp0, wv.y);
            }
            u64 xp1; PACK2(xp1, f1);
            W = Wl + (96 + 2 * kp + 1) * 16;
            #pragma unroll
            for (int i = 0; i < 16; ++i) {
                ulonglong2 wv = W[i];
                FFMA2(hacc[2 * i],     xp1, wv.x);
                FFMA2(hacc[2 * i + 1], xp1, wv.y);
            }
        }
        #pragma unroll
        for (int i = 0; i < 32; ++i) {
            float lo, hi; UNPK(lo, hi, hacc[i]);
            h[2 * i]     = fmaxf(lo, 0.f);
            h[2 * i + 1] = fmaxf(hi, 0.f);
        }
    }

    // ===== P6: proj = h @ lo2 + lob, in two 32-ch halves ==================
    float4* pdst = reinterpret_cast<float4*>(g_proj + (size_t)n * 64);
    const ulonglong2* W2 = reinterpret_cast<const ulonglong2*>(sm + OFFP_LO2);
    #pragma unroll 1
    for (int s = 0; s < 2; ++s) {
        u64 pa[16];
        {
            const u64* bp = reinterpret_cast<const u64*>(sm + OFFP_LOB) + s * 16;
            #pragma unroll
            for (int i = 0; i < 16; ++i) pa[i] = bp[i];
        }
        #pragma unroll
        for (int k = 0; k < 64; ++k) {
            u64 xp; PACK2(xp, h[k]);
            const ulonglong2* W = W2 + k * 16 + s * 8;
            #pragma unroll
            for (int i = 0; i < 8; ++i) {
                ulonglong2 wv = W[i];
                FFMA2(pa[2 * i],     xp, wv.x);
                FFMA2(pa[2 * i + 1], xp, wv.y);
            }
        }
        #pragma unroll
        for (int q = 0; q < 8; ++q) {
            float l0, h0, l1, h1;
            UNPK(l0, h0, pa[2 * q]);
            UNPK(l1, h1, pa[2 * q + 1]);
            pdst[s * 8 + q] = make_float4(l0, h0, l1, h1);
        }
    }
}

// ---------------- k3pre: sentinel-init touched tv segments + flags + lin2 --
__global__ void __launch_bounds__(256) k3pre(const int* __restrict__ bxyz,
                                             float* __restrict__ out)
{
    int w = (blockIdx.x * 256 + threadIdx.x) >> 5;
    int lane = threadIdx.x & 31;
    int4 b = reinterpret_cast<const int4*>(bxyz)[w];
    int lin2 = ((b.x * 16 + b.w) * 180 + b.z) * 240 + b.y;
    if (lane == 0) {
        g_flag[lin2] = 1;
        g_lin2[w] = lin2;
        out[(size_t)NPTS * 64 + (size_t)TVSEG * 64 + w] = (float)lin2;
    }
    if (lane < 16) {
        uint4 s = make_uint4(0xFFFFFFFFu, 0xFFFFFFFFu, 0xFFFFFFFFu, 0xFFFFFFFFu);
        reinterpret_cast<uint4*>(g_tv + (size_t)lin2 * 64)[lane] = s;
    }
}

// ---------------- k3: gather by inv + atomic segment-max -------------------
__device__ __forceinline__ void atomicMaxFloat(float* addr, float v)
{
    if (v >= 0.f) atomicMax((int*)addr, __float_as_int(v));
    else          atomicMin((unsigned int*)addr, __float_as_uint(v));
}

__global__ void __launch_bounds__(256) k3_scatter(const int* __restrict__ inv,
                                                  float* __restrict__ out)
{
    int idx = blockIdx.x * 256 + threadIdx.x;
    int n = idx >> 6, c = idx & 63;
    int src = inv[n];
    float v = g_proj[src * 64 + c];
    out[idx] = v;
    int lin2 = g_lin2[n];
    atomicMaxFloat(&g_tv[(size_t)lin2 * 64 + c], v);
}

// ---------------- k4: finalize tv -> out (flag-gated) ----------------------
__global__ void __launch_bounds__(256) k4_final(float* __restrict__ out)
{
    size_t idx = (size_t)blockIdx.x * 256 + threadIdx.x;   // float4 units
    size_t seg = idx >> 4;
    float4 v = make_float4(0.f, 0.f, 0.f, 0.f);
    if (g_flag[seg])
        v = reinterpret_cast<const float4*>(g_tv)[idx];
    reinterpret_cast<float4*>(out + (size_t)NPTS * 64)[idx] = v;
}

// ---------------- launch ---------------------------------------------------
extern "C" void kernel_launch(void* const* d_in, const int* in_sizes, int n_in,
                              void* d_out, int out_size)
{
    const float* input     = (const float*)d_in[0];
    const int*   coords    = (const int*)  d_in[1];
    const int*   inv       = (const int*)  d_in[2];
    const int*   bxyz      = (const int*)  d_in[3];
    const float* W_red     = (const float*)d_in[4];
    const float* b_red     = (const float*)d_in[5];
    const float* fc_list_W = (const float*)d_in[6];
    const float* fc_list_b = (const float*)d_in[7];
    const float* fcs_W     = (const float*)d_in[8];
    const float* fcs_b     = (const float*)d_in[9];
    const float* fc_W      = (const float*)d_in[10];
    const float* out_fc_W  = (const float*)d_in[11];
    const float* lo_W1     = (const float*)d_in[12];
    const float* lo_W2     = (const float*)d_in[13];
    const float* lo_b2     = (const float*)d_in[14];
    float* out = (float*)d_out;

    void* p;
    cudaGetSymbolAddress(&p, g_flag);
    cudaMemsetAsync(p, 0, TVSEG);
    cudaGetSymbolAddress(&p, g_segidx);
    cudaMemsetAsync(p, 0xFF, NSEG_TOTAL * sizeof(int));   // -1
    cudaGetSymbolAddress(&p, g_cnt4);
    cudaMemsetAsync(p, 0, 4 * sizeof(int));

    cudaFuncSetAttribute(k2_pt, cudaFuncAttributeMaxDynamicSharedMemorySize,
                         K2PT_SMEM);

    k0a_claim<<<3125, 256>>>(coords);                       // 800k threads
    k0b_zero<<<(4 * SEGCAP * 8) / 256, 256>>>();            // 8 thr/slot
    k1_reduce<<<25000, 256>>>(input, W_red, b_red);
    k2_seg<<<4 * 784, 256>>>(fc_list_W, fc_list_b);
    k2_pt<<<(NPTS + K2T - 1) / K2T, K2T, K2PT_SMEM>>>(fc_W, fcs_W, fcs_b,
                                                      out_fc_W, lo_W1, lo_W2,
                                                      lo_b2);
    k3pre<<<25000, 256>>>(bxyz, out);
    k3_scatter<<<50000, 256>>>(inv, out);
    k4_final<<<86400, 256>>>(out);
}